// round 1
// baseline (speedup 1.0000x reference)
#include <cuda_runtime.h>
#include <math.h>

// ---------------------------------------------------------------------------
// LiveNet fused forward, fp32 reference-accuracy version.
//   K1: h   = relu(x @ W1^T + b1)                  [32768, 1024]
//   K2: a2  = relu(h @ [W21;Wobs1]^T + [b21;bobs1]) [32768, 1024] (x21 | x22)
//   K3: layer3 dots + CBF epilogue -> out [32768, 14]
// ---------------------------------------------------------------------------

#define B_ROWS 32768
#define NUM_IN 20
#define H1     1024
#define NCAT   1024   // 512 (x21) + 512 (x22)

__device__ float g_h [(size_t)B_ROWS * H1];
__device__ float g_a2[(size_t)B_ROWS * NCAT];

// ---------------------------------------------------------------------------
// Kernel 1: layer 1.  grid (4, 512), block 256.
// Each block: 64 rows x 256 cols. Per-thread weights in registers, x tile in smem.
// ---------------------------------------------------------------------------
__global__ __launch_bounds__(256) void k1_layer1(
    const float* __restrict__ x,
    const float* __restrict__ W1,
    const float* __restrict__ b1)
{
    __shared__ float xs[64][NUM_IN];
    const int r0 = blockIdx.y * 64;
    const int c  = blockIdx.x * 256 + threadIdx.x;

    for (int i = threadIdx.x; i < 64 * NUM_IN; i += 256) {
        xs[i / NUM_IN][i % NUM_IN] = x[(size_t)(r0 + i / NUM_IN) * NUM_IN + (i % NUM_IN)];
    }

    float w[NUM_IN];
#pragma unroll
    for (int k = 0; k < NUM_IN; k++) w[k] = W1[(size_t)c * NUM_IN + k];
    const float bias = b1[c];

    __syncthreads();

#pragma unroll 4
    for (int r = 0; r < 64; r++) {
        float acc = bias;
#pragma unroll
        for (int k = 0; k < NUM_IN; k++) acc = fmaf(xs[r][k], w[k], acc);
        g_h[(size_t)(r0 + r) * H1 + c] = fmaxf(acc, 0.0f);
    }
}

// ---------------------------------------------------------------------------
// Kernel 2: fused layer-2 SGEMM, C[32768,1024] = relu(h @ Wcat^T + bcat).
// Tiles: BM=128, BN=128, BK=16; 256 threads, 8x8 accumulators per thread.
// grid (1024/128=8, 32768/128=256).
// ---------------------------------------------------------------------------
__global__ __launch_bounds__(256, 2) void k2_layer2(
    const float* __restrict__ W21,  const float* __restrict__ b21,
    const float* __restrict__ Wobs1,const float* __restrict__ bobs1)
{
    __shared__ float As[16][128];
    __shared__ float Bs[16][128];

    const int m0  = blockIdx.y * 128;
    const int n0  = blockIdx.x * 128;
    const int tid = threadIdx.x;
    const int tx  = tid & 15;      // 0..15 -> 8 cols each
    const int ty  = tid >> 4;      // 0..15 -> 8 rows each

    const int lrow = tid >> 2;         // 0..63
    const int lk4  = (tid & 3) * 4;    // 0,4,8,12

    float acc[8][8];
#pragma unroll
    for (int i = 0; i < 8; i++)
#pragma unroll
        for (int j = 0; j < 8; j++) acc[i][j] = 0.0f;

    // resolve the two global row pointers for the B tile once
    const float* wrow0;
    const float* wrow1;
    {
        int ng0 = n0 + lrow;
        int ng1 = n0 + lrow + 64;
        wrow0 = (ng0 < 512) ? (W21 + (size_t)ng0 * H1) : (Wobs1 + (size_t)(ng0 - 512) * H1);
        wrow1 = (ng1 < 512) ? (W21 + (size_t)ng1 * H1) : (Wobs1 + (size_t)(ng1 - 512) * H1);
    }

    for (int k0 = 0; k0 < H1; k0 += 16) {
        // ---- load A tile (transposed into smem) ----
#pragma unroll
        for (int p = 0; p < 2; p++) {
            int m = lrow + p * 64;
            float4 av = *(const float4*)(&g_h[(size_t)(m0 + m) * H1 + k0 + lk4]);
            As[lk4 + 0][m] = av.x;
            As[lk4 + 1][m] = av.y;
            As[lk4 + 2][m] = av.z;
            As[lk4 + 3][m] = av.w;
        }
        // ---- load B tile (transposed into smem) ----
        {
            float4 bv0 = *(const float4*)(&wrow0[k0 + lk4]);
            float4 bv1 = *(const float4*)(&wrow1[k0 + lk4]);
            Bs[lk4 + 0][lrow]      = bv0.x;
            Bs[lk4 + 1][lrow]      = bv0.y;
            Bs[lk4 + 2][lrow]      = bv0.z;
            Bs[lk4 + 3][lrow]      = bv0.w;
            Bs[lk4 + 0][lrow + 64] = bv1.x;
            Bs[lk4 + 1][lrow + 64] = bv1.y;
            Bs[lk4 + 2][lrow + 64] = bv1.z;
            Bs[lk4 + 3][lrow + 64] = bv1.w;
        }
        __syncthreads();

#pragma unroll
        for (int k = 0; k < 16; k++) {
            float a[8], b[8];
            *(float4*)&a[0] = *(const float4*)&As[k][ty * 8];
            *(float4*)&a[4] = *(const float4*)&As[k][ty * 8 + 4];
            *(float4*)&b[0] = *(const float4*)&Bs[k][tx * 8];
            *(float4*)&b[4] = *(const float4*)&Bs[k][tx * 8 + 4];
#pragma unroll
            for (int i = 0; i < 8; i++)
#pragma unroll
                for (int j = 0; j < 8; j++)
                    acc[i][j] = fmaf(a[i], b[j], acc[i][j]);
        }
        __syncthreads();
    }

    // ---- epilogue: bias + relu + store ----
    float bias_[8];
#pragma unroll
    for (int j = 0; j < 8; j++) {
        int n = n0 + tx * 8 + j;
        bias_[j] = (n < 512) ? b21[n] : bobs1[n - 512];
    }

#pragma unroll
    for (int i = 0; i < 8; i++) {
        int m = m0 + ty * 8 + i;
        float o[8];
#pragma unroll
        for (int j = 0; j < 8; j++) o[j] = fmaxf(acc[i][j] + bias_[j], 0.0f);
        size_t off = (size_t)m * NCAT + n0 + tx * 8;
        *(float4*)&g_a2[off]     = make_float4(o[0], o[1], o[2], o[3]);
        *(float4*)&g_a2[off + 4] = make_float4(o[4], o[5], o[6], o[7]);
    }
}

// ---------------------------------------------------------------------------
// Kernel 3: layer 3 + CBF epilogue. One warp per row. grid 4096, block 256.
// ---------------------------------------------------------------------------
__global__ __launch_bounds__(256) void k3_epilogue(
    const float* __restrict__ x,
    const float* __restrict__ mean_, const float* __restrict__ stdv,
    const float* __restrict__ W31,   const float* __restrict__ b31,
    const float* __restrict__ Wobs2, const float* __restrict__ bobs2,
    float* __restrict__ out)
{
    __shared__ float w31s[1024];
    __shared__ float wo2s[1024];
    for (int i = threadIdx.x; i < 1024; i += 256) {
        w31s[i] = W31[i];
        wo2s[i] = Wobs2[i];
    }
    __syncthreads();

    const int warp = threadIdx.x >> 5;
    const int lane = threadIdx.x & 31;
    const int row  = blockIdx.x * 8 + warp;

    const float* a = g_a2 + (size_t)row * NCAT;

    float s0 = 0.f, s1 = 0.f, t0 = 0.f, t1 = 0.f;
#pragma unroll
    for (int k = lane; k < 512; k += 32) {
        float v21 = a[k];
        float v22 = a[512 + k];
        s0 = fmaf(v21, w31s[k],       s0);
        s1 = fmaf(v21, w31s[512 + k], s1);
        t0 = fmaf(v22, wo2s[k],       t0);
        t1 = fmaf(v22, wo2s[512 + k], t1);
    }
#pragma unroll
    for (int off = 16; off > 0; off >>= 1) {
        s0 += __shfl_xor_sync(0xFFFFFFFFu, s0, off);
        s1 += __shfl_xor_sync(0xFFFFFFFFu, s1, off);
        t0 += __shfl_xor_sync(0xFFFFFFFFu, t0, off);
        t1 += __shfl_xor_sync(0xFFFFFFFFu, t1, off);
    }

    if (lane == 0) {
        const float x31_0 = s0 + b31[0];
        const float x31_1 = s1 + b31[1];
        const float p0 = 4.0f / (1.0f + expf(-(t0 + bobs2[0])));
        const float p1 = 4.0f / (1.0f + expf(-(t1 + bobs2[1])));

        const float* xr = x + (size_t)row * NUM_IN;
        float x0v[NUM_IN];
#pragma unroll
        for (int c = 2; c < NUM_IN; c++) x0v[c] = fmaf(xr[c], stdv[c], mean_[c]);

        const float theta = x0v[2];
        const float v     = x0v[3];
        const float st = sinf(theta), ct = cosf(theta);
        const float ox = x0v[4], oy = x0v[5], oth = x0v[6], ov = x0v[7];
        const float dx = -ox, dy = -oy;
        const float ost = sinf(oth), oct = cosf(oth);
        const float R2 = 0.45f * 0.45f;

        const float barrier = dx * dx + dy * dy - R2;
        const float bdot    = 2.0f * dx * (v * ct - ov * oct)
                            + 2.0f * dy * (v * st - ov * ost);
        const float Lf2b    = 2.0f * (v * v + ov * ov
                            - 2.0f * v * ov * cosf(theta + oth));
        const float Gu1 = -2.0f * dx * v * st + 2.0f * dy * v * ct;
        const float Gu2 =  2.0f * dx * ct + 2.0f * dy * st;

        const float psum = p0 + p1;
        const float pprod = p0 * p1;

        float o[14];
        o[0]  = x31_0;
        o[1]  = x31_1;
        o[2]  = -Gu1;
        o[3]  = -Gu2;
        o[10] = Lf2b + psum * bdot + pprod * barrier;

        const float sLf2b = 2.0f * v * v;
#pragma unroll
        for (int j = 0; j < 3; j++) {
            const float sdx = -x0v[8 + 4 * j];
            const float sdy = -x0v[9 + 4 * j];
            const float sb    = sdx * sdx + sdy * sdy - R2;
            const float sbdot = 2.0f * sdx * v * ct + 2.0f * sdy * v * st;
            const float sGu1  = -2.0f * sdx * v * st + 2.0f * sdy * v * ct;
            const float sGu2  =  2.0f * sdx * ct + 2.0f * sdy * st;
            o[4 + 2 * j]  = -sGu1;
            o[5 + 2 * j]  = -sGu2;
            o[11 + j]     = sLf2b + psum * sbdot + pprod * sb;
        }

        float* op = out + (size_t)row * 14;
#pragma unroll
        for (int i = 0; i < 14; i++) op[i] = o[i];
    }
}

// ---------------------------------------------------------------------------
// Launch
// ---------------------------------------------------------------------------
extern "C" void kernel_launch(void* const* d_in, const int* in_sizes, int n_in,
                              void* d_out, int out_size)
{
    const float* x      = (const float*)d_in[0];
    // d_in[1] = sgn (unused by reference output)
    const float* mean_  = (const float*)d_in[2];
    const float* stdv   = (const float*)d_in[3];
    const float* W1     = (const float*)d_in[4];
    const float* b1     = (const float*)d_in[5];
    const float* W21    = (const float*)d_in[6];
    const float* b21    = (const float*)d_in[7];
    const float* W31    = (const float*)d_in[8];
    const float* b31    = (const float*)d_in[9];
    const float* Wobs1  = (const float*)d_in[10];
    const float* bobs1  = (const float*)d_in[11];
    const float* Wobs2  = (const float*)d_in[12];
    const float* bobs2  = (const float*)d_in[13];
    float* out = (float*)d_out;

    k1_layer1<<<dim3(H1 / 256, B_ROWS / 64), 256>>>(x, W1, b1);
    k2_layer2<<<dim3(NCAT / 128, B_ROWS / 128), 256>>>(W21, b21, Wobs1, bobs1);
    k3_epilogue<<<B_ROWS / 8, 256>>>(x, mean_, stdv, W31, b31, Wobs2, bobs2, out);
}

// round 4
// speedup vs baseline: 3.0160x; 3.0160x over previous
#include <cuda_runtime.h>
#include <math.h>
#include <stdint.h>

// ---------------------------------------------------------------------------
// LiveNet fused forward (sm_100 plain target: no tcgen05 — use mma.sync tf32)
//   K1: h   = relu(x @ W1^T + b1)                   [32768, 1024]  fp32 FFMA
//   K2: a2  = relu(h @ [W21;Wobs1]^T + bias)        [32768, 1024]  mma.sync tf32
//   K3: layer3 dots + CBF epilogue -> out [32768, 14]
// ---------------------------------------------------------------------------

#define B_ROWS 32768
#define NUM_IN 20
#define H1     1024
#define NCAT   1024

__device__ float g_h [(size_t)B_ROWS * H1];
__device__ float g_a2[(size_t)B_ROWS * NCAT];

// ---------------------------------------------------------------------------
// Kernel 1: layer 1. grid (4, 512), block 256.
// ---------------------------------------------------------------------------
__global__ __launch_bounds__(256) void k1_layer1(
    const float* __restrict__ x,
    const float* __restrict__ W1,
    const float* __restrict__ b1)
{
    __shared__ float xs[64][NUM_IN];
    const int r0 = blockIdx.y * 64;
    const int c  = blockIdx.x * 256 + threadIdx.x;

    for (int i = threadIdx.x; i < 64 * NUM_IN; i += 256) {
        xs[i / NUM_IN][i % NUM_IN] = x[(size_t)(r0 + i / NUM_IN) * NUM_IN + (i % NUM_IN)];
    }

    float w[NUM_IN];
#pragma unroll
    for (int k = 0; k < NUM_IN; k++) w[k] = W1[(size_t)c * NUM_IN + k];
    const float bias = b1[c];

    __syncthreads();

#pragma unroll 4
    for (int r = 0; r < 64; r++) {
        float acc = bias;
#pragma unroll
        for (int k = 0; k < NUM_IN; k++) acc = fmaf(xs[r][k], w[k], acc);
        g_h[(size_t)(r0 + r) * H1 + c] = fmaxf(acc, 0.0f);
    }
}

// ---------------------------------------------------------------------------
// Kernel 2: mma.sync tf32 GEMM. BM=128, BN=128, BK=32, double-buffered,
// one __syncthreads per K-slab. grid (8, 256), block 256 (8 warps).
// Warp tile 32x64 = 2 m-tiles x 8 n-tiles of m16n8k8.
// ---------------------------------------------------------------------------
#define SSTR   36                 // smem row stride in floats (32 + 4 pad)
#define TILE_F (128 * SSTR)       // floats per (A or B) buffer
#define K2_SMEM_BYTES (4 * TILE_F * 4)   // 2 bufs x (A+B) = 73728 B

__device__ __forceinline__ uint32_t f2tf(float f) {
    uint32_t r;
    asm("cvt.rna.tf32.f32 %0, %1;" : "=r"(r) : "f"(f));
    return r;
}

__device__ __forceinline__ void mma8(float* c, const uint32_t* a, const uint32_t* b) {
    asm volatile(
        "mma.sync.aligned.m16n8k8.row.col.f32.tf32.tf32.f32 "
        "{%0,%1,%2,%3}, {%4,%5,%6,%7}, {%8,%9}, {%0,%1,%2,%3};"
        : "+f"(c[0]), "+f"(c[1]), "+f"(c[2]), "+f"(c[3])
        : "r"(a[0]), "r"(a[1]), "r"(a[2]), "r"(a[3]), "r"(b[0]), "r"(b[1]));
}

__global__ __launch_bounds__(256) void k2_mma(
    const float* __restrict__ W21,  const float* __restrict__ b21,
    const float* __restrict__ Wobs1,const float* __restrict__ bobs1)
{
    extern __shared__ float sm[];
    float* As = sm;                // As[buf] = sm + buf*TILE_F
    float* Bs = sm + 2 * TILE_F;   // Bs[buf] = ... + buf*TILE_F

    const int tid  = threadIdx.x;
    const int wid  = tid >> 5;
    const int lane = tid & 31;
    const int g    = lane >> 2;    // 0..7
    const int t    = lane & 3;     // 0..3
    const int wm   = (wid & 3) * 32;   // warp m offset in tile
    const int wn   = (wid >> 2) * 64;  // warp n offset in tile

    const int m0 = blockIdx.y * 128;
    const int n0 = blockIdx.x * 128;

    const float* Wsrc = (n0 < 512) ? (W21 + (size_t)n0 * H1)
                                   : (Wobs1 + (size_t)(n0 - 512) * H1);
    const float* bsrc = (n0 < 512) ? (b21 + n0) : (bobs1 + (n0 - 512));

    // gmem load mapping: lm = tid>>3 (row 0..31, +32*i), lkq = tid&7 (float4 chunk)
    const int lm  = tid >> 3;
    const int lkq = tid & 7;
    const float* aG = &g_h[(size_t)(m0 + lm) * H1 + lkq * 4];
    const float* bG = &Wsrc[(size_t)lm * H1 + lkq * 4];

    float4 ra[4], rb[4];
    float acc[2][8][4];
#pragma unroll
    for (int mt = 0; mt < 2; mt++)
#pragma unroll
        for (int nt = 0; nt < 8; nt++)
#pragma unroll
            for (int j = 0; j < 4; j++) acc[mt][nt][j] = 0.0f;

    // ---------- prologue: load slab 0 ----------
#pragma unroll
    for (int i = 0; i < 4; i++) {
        ra[i] = *(const float4*)(aG + (size_t)i * 32 * H1);
        rb[i] = *(const float4*)(bG + (size_t)i * 32 * H1);
    }
    {
        float* Ad = As + lm * SSTR + lkq * 4;
        float* Bd = Bs + lm * SSTR + lkq * 4;
#pragma unroll
        for (int i = 0; i < 4; i++) {
            float4 va = ra[i], vb = rb[i];
            float4 ca = make_float4(__uint_as_float(f2tf(va.x)), __uint_as_float(f2tf(va.y)),
                                    __uint_as_float(f2tf(va.z)), __uint_as_float(f2tf(va.w)));
            float4 cb = make_float4(__uint_as_float(f2tf(vb.x)), __uint_as_float(f2tf(vb.y)),
                                    __uint_as_float(f2tf(vb.z)), __uint_as_float(f2tf(vb.w)));
            *(float4*)(Ad + i * 32 * SSTR) = ca;
            *(float4*)(Bd + i * 32 * SSTR) = cb;
        }
    }
    __syncthreads();

    // ---------- main pipeline: 32 slabs of BK=32 ----------
    for (int s = 0; s < 32; s++) {
        const int cur = s & 1;
        const int nxt = cur ^ 1;

        if (s < 31) {
            const int ko = (s + 1) * 32;
#pragma unroll
            for (int i = 0; i < 4; i++) {
                ra[i] = *(const float4*)(aG + (size_t)i * 32 * H1 + ko);
                rb[i] = *(const float4*)(bG + (size_t)i * 32 * H1 + ko);
            }
        }

        // ---- compute on buffer cur ----
        {
            const float* Ab = As + cur * TILE_F;
            const float* Bb = Bs + cur * TILE_F;
#pragma unroll
            for (int ks = 0; ks < 4; ks++) {
                const int k0 = ks * 8;
                uint32_t af[2][4];
#pragma unroll
                for (int mt = 0; mt < 2; mt++) {
                    const float* ap = Ab + (wm + mt * 16 + g) * SSTR + k0 + t;
                    af[mt][0] = __float_as_uint(ap[0]);
                    af[mt][1] = __float_as_uint(ap[8 * SSTR]);
                    af[mt][2] = __float_as_uint(ap[4]);
                    af[mt][3] = __float_as_uint(ap[8 * SSTR + 4]);
                }
#pragma unroll
                for (int nt = 0; nt < 8; nt++) {
                    const float* bp = Bb + (wn + nt * 8 + g) * SSTR + k0 + t;
                    uint32_t bf[2];
                    bf[0] = __float_as_uint(bp[0]);
                    bf[1] = __float_as_uint(bp[4]);
                    mma8(acc[0][nt], af[0], bf);
                    mma8(acc[1][nt], af[1], bf);
                }
            }
        }

        if (s < 31) {
            float* Ad = As + nxt * TILE_F + lm * SSTR + lkq * 4;
            float* Bd = Bs + nxt * TILE_F + lm * SSTR + lkq * 4;
#pragma unroll
            for (int i = 0; i < 4; i++) {
                float4 va = ra[i], vb = rb[i];
                float4 ca = make_float4(__uint_as_float(f2tf(va.x)), __uint_as_float(f2tf(va.y)),
                                        __uint_as_float(f2tf(va.z)), __uint_as_float(f2tf(va.w)));
                float4 cb = make_float4(__uint_as_float(f2tf(vb.x)), __uint_as_float(f2tf(vb.y)),
                                        __uint_as_float(f2tf(vb.z)), __uint_as_float(f2tf(vb.w)));
                *(float4*)(Ad + i * 32 * SSTR) = ca;
                *(float4*)(Bd + i * 32 * SSTR) = cb;
            }
        }
        __syncthreads();
    }

    // ---------- epilogue: bias + relu + float2 stores ----------
#pragma unroll
    for (int nt = 0; nt < 8; nt++) {
        const float2 bb = *(const float2*)&bsrc[wn + nt * 8 + t * 2];
        const int ncol = n0 + wn + nt * 8 + t * 2;
#pragma unroll
        for (int mt = 0; mt < 2; mt++) {
            const int row0 = m0 + wm + mt * 16 + g;
            float2 v0, v1;
            v0.x = fmaxf(acc[mt][nt][0] + bb.x, 0.0f);
            v0.y = fmaxf(acc[mt][nt][1] + bb.y, 0.0f);
            v1.x = fmaxf(acc[mt][nt][2] + bb.x, 0.0f);
            v1.y = fmaxf(acc[mt][nt][3] + bb.y, 0.0f);
            *(float2*)&g_a2[(size_t)row0 * NCAT + ncol]       = v0;
            *(float2*)&g_a2[(size_t)(row0 + 8) * NCAT + ncol] = v1;
        }
    }
}

// ---------------------------------------------------------------------------
// Kernel 3: layer 3 + CBF epilogue. One warp per row. grid 4096, block 256.
// ---------------------------------------------------------------------------
__global__ __launch_bounds__(256) void k3_epilogue(
    const float* __restrict__ x,
    const float* __restrict__ mean_, const float* __restrict__ stdv,
    const float* __restrict__ W31,   const float* __restrict__ b31,
    const float* __restrict__ Wobs2, const float* __restrict__ bobs2,
    float* __restrict__ out)
{
    __shared__ float w31s[1024];
    __shared__ float wo2s[1024];
    for (int i = threadIdx.x; i < 1024; i += 256) {
        w31s[i] = W31[i];
        wo2s[i] = Wobs2[i];
    }
    __syncthreads();

    const int warp = threadIdx.x >> 5;
    const int lane = threadIdx.x & 31;
    const int row  = blockIdx.x * 8 + warp;

    const float* a = g_a2 + (size_t)row * NCAT;

    float s0 = 0.f, s1 = 0.f, t0 = 0.f, t1 = 0.f;
#pragma unroll
    for (int k = lane; k < 512; k += 32) {
        float v21 = a[k];
        float v22 = a[512 + k];
        s0 = fmaf(v21, w31s[k],       s0);
        s1 = fmaf(v21, w31s[512 + k], s1);
        t0 = fmaf(v22, wo2s[k],       t0);
        t1 = fmaf(v22, wo2s[512 + k], t1);
    }
#pragma unroll
    for (int off = 16; off > 0; off >>= 1) {
        s0 += __shfl_xor_sync(0xFFFFFFFFu, s0, off);
        s1 += __shfl_xor_sync(0xFFFFFFFFu, s1, off);
        t0 += __shfl_xor_sync(0xFFFFFFFFu, t0, off);
        t1 += __shfl_xor_sync(0xFFFFFFFFu, t1, off);
    }

    if (lane == 0) {
        const float x31_0 = s0 + b31[0];
        const float x31_1 = s1 + b31[1];
        const float p0 = 4.0f / (1.0f + expf(-(t0 + bobs2[0])));
        const float p1 = 4.0f / (1.0f + expf(-(t1 + bobs2[1])));

        const float* xr = x + (size_t)row * NUM_IN;
        float x0v[NUM_IN];
#pragma unroll
        for (int c = 2; c < NUM_IN; c++) x0v[c] = fmaf(xr[c], stdv[c], mean_[c]);

        const float theta = x0v[2];
        const float v     = x0v[3];
        const float st = sinf(theta), ct = cosf(theta);
        const float ox = x0v[4], oy = x0v[5], oth = x0v[6], ov = x0v[7];
        const float dx = -ox, dy = -oy;
        const float ost = sinf(oth), oct = cosf(oth);
        const float R2 = 0.45f * 0.45f;

        const float barrier = dx * dx + dy * dy - R2;
        const float bdot    = 2.0f * dx * (v * ct - ov * oct)
                            + 2.0f * dy * (v * st - ov * ost);
        const float Lf2b    = 2.0f * (v * v + ov * ov
                            - 2.0f * v * ov * cosf(theta + oth));
        const float Gu1 = -2.0f * dx * v * st + 2.0f * dy * v * ct;
        const float Gu2 =  2.0f * dx * ct + 2.0f * dy * st;

        const float psum = p0 + p1;
        const float pprod = p0 * p1;

        float o[14];
        o[0]  = x31_0;
        o[1]  = x31_1;
        o[2]  = -Gu1;
        o[3]  = -Gu2;
        o[10] = Lf2b + psum * bdot + pprod * barrier;

        const float sLf2b = 2.0f * v * v;
#pragma unroll
        for (int j = 0; j < 3; j++) {
            const float sdx = -x0v[8 + 4 * j];
            const float sdy = -x0v[9 + 4 * j];
            const float sb    = sdx * sdx + sdy * sdy - R2;
            const float sbdot = 2.0f * sdx * v * ct + 2.0f * sdy * v * st;
            const float sGu1  = -2.0f * sdx * v * st + 2.0f * sdy * v * ct;
            const float sGu2  =  2.0f * sdx * ct + 2.0f * sdy * st;
            o[4 + 2 * j]  = -sGu1;
            o[5 + 2 * j]  = -sGu2;
            o[11 + j]     = sLf2b + psum * sbdot + pprod * sb;
        }

        float* op = out + (size_t)row * 14;
#pragma unroll
        for (int i = 0; i < 14; i++) op[i] = o[i];
    }
}

// ---------------------------------------------------------------------------
// Launch
// ---------------------------------------------------------------------------
extern "C" void kernel_launch(void* const* d_in, const int* in_sizes, int n_in,
                              void* d_out, int out_size)
{
    const float* x      = (const float*)d_in[0];
    const float* mean_  = (const float*)d_in[2];
    const float* stdv   = (const float*)d_in[3];
    const float* W1     = (const float*)d_in[4];
    const float* b1     = (const float*)d_in[5];
    const float* W21    = (const float*)d_in[6];
    const float* b21    = (const float*)d_in[7];
    const float* W31    = (const float*)d_in[8];
    const float* b31    = (const float*)d_in[9];
    const float* Wobs1  = (const float*)d_in[10];
    const float* bobs1  = (const float*)d_in[11];
    const float* Wobs2  = (const float*)d_in[12];
    const float* bobs2  = (const float*)d_in[13];
    float* out = (float*)d_out;

    cudaFuncSetAttribute(k2_mma, cudaFuncAttributeMaxDynamicSharedMemorySize,
                         K2_SMEM_BYTES);

    k1_layer1<<<dim3(H1 / 256, B_ROWS / 64), 256>>>(x, W1, b1);
    k2_mma<<<dim3(NCAT / 128, B_ROWS / 128), 256, K2_SMEM_BYTES>>>(W21, b21, Wobs1, bobs1);
    k3_epilogue<<<B_ROWS / 8, 256>>>(x, mean_, stdv, W31, b31, Wobs2, bobs2, out);
}

// round 5
// speedup vs baseline: 3.2576x; 1.0801x over previous
#include <cuda_runtime.h>
#include <math.h>
#include <stdint.h>

// ---------------------------------------------------------------------------
// LiveNet fused forward (sm_100 plain target: mma.sync tf32, cp.async).
//   K1 : h = relu(x @ W1^T + b1)                        [32768,1024] fp32
//   K2 : tf32 GEMM over [W21;Wobs1], fused relu + layer-3 partial dots
//        -> g_part[row][16]   (no a2 materialization)
//   K3': sum partials, sigmoid, CBF epilogue -> out [32768, 14]
// ---------------------------------------------------------------------------

#define B_ROWS 32768
#define NUM_IN 20
#define H1     1024

__device__ float g_h   [(size_t)B_ROWS * H1];
__device__ float g_part[(size_t)B_ROWS * 16];

// ---------------------------------------------------------------------------
// Kernel 1: layer 1. grid (4, 512), block 256.
// ---------------------------------------------------------------------------
__global__ __launch_bounds__(256) void k1_layer1(
    const float* __restrict__ x,
    const float* __restrict__ W1,
    const float* __restrict__ b1)
{
    __shared__ float xs[64][NUM_IN];
    const int r0 = blockIdx.y * 64;
    const int c  = blockIdx.x * 256 + threadIdx.x;

    for (int i = threadIdx.x; i < 64 * NUM_IN; i += 256) {
        xs[i / NUM_IN][i % NUM_IN] = x[(size_t)(r0 + i / NUM_IN) * NUM_IN + (i % NUM_IN)];
    }

    float w[NUM_IN];
#pragma unroll
    for (int k = 0; k < NUM_IN; k++) w[k] = W1[(size_t)c * NUM_IN + k];
    const float bias = b1[c];

    __syncthreads();

#pragma unroll 4
    for (int r = 0; r < 64; r++) {
        float acc = bias;
#pragma unroll
        for (int k = 0; k < NUM_IN; k++) acc = fmaf(xs[r][k], w[k], acc);
        g_h[(size_t)(r0 + r) * H1 + c] = fmaxf(acc, 0.0f);
    }
}

// ---------------------------------------------------------------------------
// Kernel 2: tf32 mma.sync GEMM, BM=128, BN=128, BK=32, 3-stage cp.async.
// grid (8, 256), block 256 (8 warps, warp tile 32x64).
// Epilogue: relu + partial layer-3 dots -> g_part.
// ---------------------------------------------------------------------------
#define SSTR     36                    // smem row stride (floats): 32 + 4 pad
#define TILE_F   (128 * SSTR)          // 4608 floats = 18432 B per A or B tile
#define STAGE_F  (2 * TILE_F)          // 9216 floats per stage
#define K2_SMEM_BYTES (3 * STAGE_F * 4)  // 110592 B

__device__ __forceinline__ void cpa_cg(uint32_t d, const float* s) {
    asm volatile("cp.async.cg.shared.global [%0], [%1], 16;" :: "r"(d), "l"(s));
}
__device__ __forceinline__ void cpa_ca(uint32_t d, const float* s) {
    asm volatile("cp.async.ca.shared.global [%0], [%1], 16;" :: "r"(d), "l"(s));
}

__device__ __forceinline__ void mma8(float* c, const uint32_t* a, const uint32_t* b) {
    asm volatile(
        "mma.sync.aligned.m16n8k8.row.col.f32.tf32.tf32.f32 "
        "{%0,%1,%2,%3}, {%4,%5,%6,%7}, {%8,%9}, {%0,%1,%2,%3};"
        : "+f"(c[0]), "+f"(c[1]), "+f"(c[2]), "+f"(c[3])
        : "r"(a[0]), "r"(a[1]), "r"(a[2]), "r"(a[3]), "r"(b[0]), "r"(b[1]));
}

__global__ __launch_bounds__(256) void k2_mma(
    const float* __restrict__ W21,  const float* __restrict__ b21,
    const float* __restrict__ Wobs1,const float* __restrict__ bobs1,
    const float* __restrict__ W31,  const float* __restrict__ Wobs2)
{
    extern __shared__ float sm[];
    __shared__ float ws[2][128];          // layer-3 weight slice for this n-range
    __shared__ float sred[2][128][2];     // cross-warp partial reduction

    const int tid  = threadIdx.x;
    const int wid  = tid >> 5;
    const int lane = tid & 31;
    const int g    = lane >> 2;        // 0..7
    const int t    = lane & 3;         // 0..3
    const int wm   = (wid & 3) * 32;   // warp m offset
    const int wn   = (wid >> 2) * 64;  // warp n offset
    const int half = wid >> 2;

    const int m0 = blockIdx.y * 128;
    const int n0 = blockIdx.x * 128;
    const int pair = (n0 >= 512);      // 0: x21/W31 region, 1: x22/Wobs2

    const float* Wsrc = pair ? (Wobs1 + (size_t)(n0 - 512) * H1)
                             : (W21 + (size_t)n0 * H1);
    const float* bsrc = pair ? (bobs1 + (n0 - 512)) : (b21 + n0);
    const float* w0g  = pair ? (Wobs2 + (n0 - 512)) : (W31 + n0);
    const float* w1g  = pair ? (Wobs2 + 512 + (n0 - 512)) : (W31 + 512 + n0);

    // gmem load mapping: 16B chunk per cp.async
    const int lm  = tid >> 3;          // 0..31 (row, +32*i)
    const int lkq = tid & 7;           // float4 chunk in K
    const float* aG = &g_h[(size_t)(m0 + lm) * H1 + lkq * 4];
    const float* bG = &Wsrc[(size_t)lm * H1 + lkq * 4];

    uint32_t smem_base;
    asm("{ .reg .u64 t; cvta.to.shared.u64 t, %1; cvt.u32.u64 %0, t; }"
        : "=r"(smem_base) : "l"(sm));
    const uint32_t dOff = (uint32_t)(lm * SSTR * 4 + lkq * 16);

    float acc[2][8][4];
#pragma unroll
    for (int mt = 0; mt < 2; mt++)
#pragma unroll
        for (int nt = 0; nt < 8; nt++)
#pragma unroll
            for (int j = 0; j < 4; j++) acc[mt][nt][j] = 0.0f;

    // ---- prologue: stages 0,1 ----
#pragma unroll
    for (int p = 0; p < 2; p++) {
        const uint32_t aB = smem_base + p * (STAGE_F * 4) + dOff;
        const uint32_t bB = aB + (uint32_t)(TILE_F * 4);
        const int k0 = p * 32;
#pragma unroll
        for (int i = 0; i < 4; i++) {
            cpa_cg(aB + i * 32 * SSTR * 4, aG + (size_t)i * 32 * H1 + k0);
            cpa_ca(bB + i * 32 * SSTR * 4, bG + (size_t)i * 32 * H1 + k0);
        }
        asm volatile("cp.async.commit_group;");
    }

    // ---- main loop: 32 slabs ----
    int stg = 0;
    for (int s = 0; s < 32; s++) {
        asm volatile("cp.async.wait_group 1;");
        __syncthreads();

        if (s < 30) {
            const int pst = (stg + 2 >= 3) ? (stg - 1) : (stg + 2);
            const uint32_t aB = smem_base + pst * (STAGE_F * 4) + dOff;
            const uint32_t bB = aB + (uint32_t)(TILE_F * 4);
            const int k0 = (s + 2) * 32;
#pragma unroll
            for (int i = 0; i < 4; i++) {
                cpa_cg(aB + i * 32 * SSTR * 4, aG + (size_t)i * 32 * H1 + k0);
                cpa_ca(bB + i * 32 * SSTR * 4, bG + (size_t)i * 32 * H1 + k0);
            }
        }
        asm volatile("cp.async.commit_group;");

        // ---- compute stage stg ----
        {
            const float* Ab = sm + stg * STAGE_F;
            const float* Bb = Ab + TILE_F;
#pragma unroll
            for (int ks = 0; ks < 4; ks++) {
                const int k0 = ks * 8;
                uint32_t af[2][4];
#pragma unroll
                for (int mt = 0; mt < 2; mt++) {
                    const float* ap = Ab + (wm + mt * 16 + g) * SSTR + k0 + t;
                    af[mt][0] = __float_as_uint(ap[0]);
                    af[mt][1] = __float_as_uint(ap[8 * SSTR]);
                    af[mt][2] = __float_as_uint(ap[4]);
                    af[mt][3] = __float_as_uint(ap[8 * SSTR + 4]);
                }
#pragma unroll
                for (int nt = 0; nt < 8; nt++) {
                    const float* bp = Bb + (wn + nt * 8 + g) * SSTR + k0 + t;
                    uint32_t bf[2];
                    bf[0] = __float_as_uint(bp[0]);
                    bf[1] = __float_as_uint(bp[4]);
                    mma8(acc[0][nt], af[0], bf);
                    mma8(acc[1][nt], af[1], bf);
                }
            }
        }
        stg = (stg == 2) ? 0 : stg + 1;
    }

    // ---- epilogue: relu + partial layer-3 dots ----
    if (tid < 128) ws[0][tid] = w0g[tid];
    else           ws[1][tid - 128] = w1g[tid - 128];
    __syncthreads();

    float u[4][2];
#pragma unroll
    for (int q = 0; q < 4; q++) { u[q][0] = 0.0f; u[q][1] = 0.0f; }

#pragma unroll
    for (int nt = 0; nt < 8; nt++) {
        const int col = wn + nt * 8 + t * 2;
        const float2 bb = *(const float2*)&bsrc[col];
        const float wa0 = ws[0][col], wa1 = ws[0][col + 1];
        const float wb0 = ws[1][col], wb1 = ws[1][col + 1];
#pragma unroll
        for (int q = 0; q < 4; q++) {
            const int mt = q >> 1, h = q & 1;
            const float v0 = fmaxf(acc[mt][nt][h * 2 + 0] + bb.x, 0.0f);
            const float v1 = fmaxf(acc[mt][nt][h * 2 + 1] + bb.y, 0.0f);
            u[q][0] = fmaf(v0, wa0, fmaf(v1, wa1, u[q][0]));
            u[q][1] = fmaf(v0, wb0, fmaf(v1, wb1, u[q][1]));
        }
    }

    // reduce across t (4 lanes per group)
#pragma unroll
    for (int q = 0; q < 4; q++)
#pragma unroll
        for (int c = 0; c < 2; c++) {
            u[q][c] += __shfl_xor_sync(0xFFFFFFFFu, u[q][c], 1);
            u[q][c] += __shfl_xor_sync(0xFFFFFFFFu, u[q][c], 2);
        }

    if (t == 0) {
#pragma unroll
        for (int q = 0; q < 4; q++) {
            const int row = wm + (q >> 1) * 16 + (q & 1) * 8 + g;
            sred[half][row][0] = u[q][0];
            sred[half][row][1] = u[q][1];
        }
    }
    __syncthreads();

    {
        const int row = tid >> 1;
        const int c   = tid & 1;
        const float sum = sred[0][row][c] + sred[1][row][c];
        const int nb4 = blockIdx.x & 3;
        g_part[(size_t)(m0 + row) * 16 + pair * 8 + nb4 * 2 + c] = sum;
    }
}

// ---------------------------------------------------------------------------
// Kernel 3': per-row partial sum + sigmoid + CBF epilogue. grid 128, block 256.
// ---------------------------------------------------------------------------
__global__ __launch_bounds__(256) void k3_final(
    const float* __restrict__ x,
    const float* __restrict__ mean_, const float* __restrict__ stdv,
    const float* __restrict__ b31,   const float* __restrict__ bobs2,
    float* __restrict__ out)
{
    const int row = blockIdx.x * 256 + threadIdx.x;

    const float* pp = &g_part[(size_t)row * 16];
    float4 pa = *(const float4*)&pp[0];
    float4 pb = *(const float4*)&pp[4];
    float4 pc = *(const float4*)&pp[8];
    float4 pd = *(const float4*)&pp[12];

    const float x31_0 = pa.x + pa.z + pb.x + pb.z + b31[0];
    const float x31_1 = pa.y + pa.w + pb.y + pb.w + b31[1];
    const float t0    = pc.x + pc.z + pd.x + pd.z + bobs2[0];
    const float t1    = pc.y + pc.w + pd.y + pd.w + bobs2[1];
    const float p0 = 4.0f / (1.0f + expf(-t0));
    const float p1 = 4.0f / (1.0f + expf(-t1));

    const float* xr = x + (size_t)row * NUM_IN;
    float x0v[NUM_IN];
#pragma unroll
    for (int c = 2; c < NUM_IN; c++) x0v[c] = fmaf(xr[c], stdv[c], mean_[c]);

    const float theta = x0v[2];
    const float v     = x0v[3];
    const float st = sinf(theta), ct = cosf(theta);
    const float ox = x0v[4], oy = x0v[5], oth = x0v[6], ov = x0v[7];
    const float dx = -ox, dy = -oy;
    const float ost = sinf(oth), oct = cosf(oth);
    const float R2 = 0.45f * 0.45f;

    const float barrier = dx * dx + dy * dy - R2;
    const float bdot    = 2.0f * dx * (v * ct - ov * oct)
                        + 2.0f * dy * (v * st - ov * ost);
    const float Lf2b    = 2.0f * (v * v + ov * ov
                        - 2.0f * v * ov * cosf(theta + oth));
    const float Gu1 = -2.0f * dx * v * st + 2.0f * dy * v * ct;
    const float Gu2 =  2.0f * dx * ct + 2.0f * dy * st;

    const float psum  = p0 + p1;
    const float pprod = p0 * p1;

    float o[14];
    o[0]  = x31_0;
    o[1]  = x31_1;
    o[2]  = -Gu1;
    o[3]  = -Gu2;
    o[10] = Lf2b + psum * bdot + pprod * barrier;

    const float sLf2b = 2.0f * v * v;
#pragma unroll
    for (int j = 0; j < 3; j++) {
        const float sdx = -x0v[8 + 4 * j];
        const float sdy = -x0v[9 + 4 * j];
        const float sb    = sdx * sdx + sdy * sdy - R2;
        const float sbdot = 2.0f * sdx * v * ct + 2.0f * sdy * v * st;
        const float sGu1  = -2.0f * sdx * v * st + 2.0f * sdy * v * ct;
        const float sGu2  =  2.0f * sdx * ct + 2.0f * sdy * st;
        o[4 + 2 * j] = -sGu1;
        o[5 + 2 * j] = -sGu2;
        o[11 + j]    = sLf2b + psum * sbdot + pprod * sb;
    }

    float* op = out + (size_t)row * 14;
#pragma unroll
    for (int i = 0; i < 14; i++) op[i] = o[i];
}

// ---------------------------------------------------------------------------
// Launch
// ---------------------------------------------------------------------------
extern "C" void kernel_launch(void* const* d_in, const int* in_sizes, int n_in,
                              void* d_out, int out_size)
{
    const float* x      = (const float*)d_in[0];
    const float* mean_  = (const float*)d_in[2];
    const float* stdv   = (const float*)d_in[3];
    const float* W1     = (const float*)d_in[4];
    const float* b1     = (const float*)d_in[5];
    const float* W21    = (const float*)d_in[6];
    const float* b21    = (const float*)d_in[7];
    const float* W31    = (const float*)d_in[8];
    const float* b31    = (const float*)d_in[9];
    const float* Wobs1  = (const float*)d_in[10];
    const float* bobs1  = (const float*)d_in[11];
    const float* Wobs2  = (const float*)d_in[12];
    const float* bobs2  = (const float*)d_in[13];
    float* out = (float*)d_out;

    cudaFuncSetAttribute(k2_mma, cudaFuncAttributeMaxDynamicSharedMemorySize,
                         K2_SMEM_BYTES);

    k1_layer1<<<dim3(H1 / 256, B_ROWS / 64), 256>>>(x, W1, b1);
    k2_mma<<<dim3(8, B_ROWS / 128), 256, K2_SMEM_BYTES>>>(
        W21, b21, Wobs1, bobs1, W31, Wobs2);
    k3_final<<<B_ROWS / 256, 256>>>(x, mean_, stdv, b31, bobs2, out);
}

// round 6
// speedup vs baseline: 5.2657x; 1.6164x over previous
#include <cuda_runtime.h>
#include <cuda_fp16.h>
#include <math.h>
#include <stdint.h>

// ---------------------------------------------------------------------------
// LiveNet fused forward (sm_100 plain target; fp16 mma.sync m16n8k16).
//   K0 : convert [W21;Wobs1] fp32 -> fp16 g_wh                 [1024,1024]
//   K1 : h = relu(x @ W1^T + b1) -> g_h (fp16)                 [32768,1024]
//   K2 : fp16 GEMM h @ g_wh^T, fused relu + layer-3 partial dots -> g_part
//   K3 : sum partials, sigmoid, CBF epilogue -> out [32768,14]
// ---------------------------------------------------------------------------

#define B_ROWS 32768
#define NUM_IN 20
#define H1     1024

__device__ __half g_h [(size_t)B_ROWS * H1];
__device__ __half g_wh[(size_t)1024 * H1];
__device__ float  g_part[(size_t)B_ROWS * 16];

// ---------------------------------------------------------------------------
// Kernel 0: weight conversion. grid 1024, block 256, 4 elems/thread.
// ---------------------------------------------------------------------------
__global__ __launch_bounds__(256) void k0_convert(
    const float* __restrict__ W21, const float* __restrict__ Wobs1)
{
    const size_t i4 = ((size_t)blockIdx.x * 256 + threadIdx.x) * 4;
    const size_t half_total = (size_t)512 * H1;
    const float* src = (i4 < half_total) ? (W21 + i4) : (Wobs1 + (i4 - half_total));
    float4 v = *(const float4*)src;
    __half2* dst = (__half2*)&g_wh[i4];
    dst[0] = __floats2half2_rn(v.x, v.y);
    dst[1] = __floats2half2_rn(v.z, v.w);
}

// ---------------------------------------------------------------------------
// Kernel 1: layer 1, fp16 output. grid (2, 512), block 256.
// Each thread: 2 adjacent output columns x 64 rows -> half2 stores.
// ---------------------------------------------------------------------------
__global__ __launch_bounds__(256) void k1_layer1(
    const float* __restrict__ x,
    const float* __restrict__ W1,
    const float* __restrict__ b1)
{
    __shared__ float xs[64][NUM_IN];
    const int r0 = blockIdx.y * 64;
    const int c0 = (blockIdx.x * 256 + threadIdx.x) * 2;

    for (int i = threadIdx.x; i < 64 * NUM_IN; i += 256) {
        xs[i / NUM_IN][i % NUM_IN] = x[(size_t)(r0 + i / NUM_IN) * NUM_IN + (i % NUM_IN)];
    }

    float w0[NUM_IN], w1[NUM_IN];
#pragma unroll
    for (int k = 0; k < NUM_IN; k++) {
        w0[k] = W1[(size_t)c0 * NUM_IN + k];
        w1[k] = W1[(size_t)(c0 + 1) * NUM_IN + k];
    }
    const float bias0 = b1[c0], bias1 = b1[c0 + 1];

    __syncthreads();

#pragma unroll 4
    for (int r = 0; r < 64; r++) {
        float a0 = bias0, a1 = bias1;
#pragma unroll
        for (int k = 0; k < NUM_IN; k++) {
            const float xv = xs[r][k];
            a0 = fmaf(xv, w0[k], a0);
            a1 = fmaf(xv, w1[k], a1);
        }
        *(__half2*)&g_h[(size_t)(r0 + r) * H1 + c0] =
            __floats2half2_rn(fmaxf(a0, 0.0f), fmaxf(a1, 0.0f));
    }
}

// ---------------------------------------------------------------------------
// Kernel 2: fp16 mma.sync GEMM. BM=128, BN=128, BK=32, 4-stage cp.async.
// grid (8, 256), block 256 (8 warps, warp tile 32x64, k-step 16).
// ---------------------------------------------------------------------------
#define SSTRH    40                      // smem row stride in halfs (32 + 8 pad)
#define TILE_H   (128 * SSTRH)           // 5120 halfs = 10240 B
#define STAGE_H  (2 * TILE_H)            // A+B per stage
#define K2_SMEM_BYTES (4 * STAGE_H * 2)  // 81920 B

__device__ __forceinline__ void cpa_cg(uint32_t d, const __half* s) {
    asm volatile("cp.async.cg.shared.global [%0], [%1], 16;" :: "r"(d), "l"(s));
}
__device__ __forceinline__ void cpa_ca(uint32_t d, const __half* s) {
    asm volatile("cp.async.ca.shared.global [%0], [%1], 16;" :: "r"(d), "l"(s));
}

__device__ __forceinline__ void mma16(float* c, const uint32_t* a, const uint32_t* b) {
    asm volatile(
        "mma.sync.aligned.m16n8k16.row.col.f32.f16.f16.f32 "
        "{%0,%1,%2,%3}, {%4,%5,%6,%7}, {%8,%9}, {%0,%1,%2,%3};"
        : "+f"(c[0]), "+f"(c[1]), "+f"(c[2]), "+f"(c[3])
        : "r"(a[0]), "r"(a[1]), "r"(a[2]), "r"(a[3]), "r"(b[0]), "r"(b[1]));
}

__global__ __launch_bounds__(256, 2) void k2_mma(
    const float* __restrict__ b21,  const float* __restrict__ bobs1,
    const float* __restrict__ W31,  const float* __restrict__ Wobs2)
{
    extern __shared__ __half smh[];
    __shared__ float ws[2][128];
    __shared__ float sred[2][128][2];

    const int tid  = threadIdx.x;
    const int wid  = tid >> 5;
    const int lane = tid & 31;
    const int g    = lane >> 2;
    const int t    = lane & 3;
    const int wm   = (wid & 3) * 32;
    const int wn   = (wid >> 2) * 64;
    const int half = wid >> 2;

    const int m0 = blockIdx.y * 128;
    const int n0 = blockIdx.x * 128;
    const int pair = (n0 >= 512);

    const float* bsrc = pair ? (bobs1 + (n0 - 512)) : (b21 + n0);
    const float* w0g  = pair ? (Wobs2 + (n0 - 512)) : (W31 + n0);
    const float* w1g  = pair ? (Wobs2 + 512 + (n0 - 512)) : (W31 + 512 + n0);

    // cp.async mapping: lm = row (0..63, +64), lq = 16B chunk (8 halfs)
    const int lm = tid >> 2;
    const int lq = tid & 3;
    const __half* aG = &g_h [(size_t)(m0 + lm) * H1 + lq * 8];
    const __half* bG = &g_wh[(size_t)(n0 + lm) * H1 + lq * 8];

    uint32_t smem_base;
    asm("{ .reg .u64 t; cvta.to.shared.u64 t, %1; cvt.u32.u64 %0, t; }"
        : "=r"(smem_base) : "l"(smh));
    const uint32_t dOff = (uint32_t)(lm * SSTRH * 2 + lq * 16);

    float acc[2][8][4];
#pragma unroll
    for (int mt = 0; mt < 2; mt++)
#pragma unroll
        for (int nt = 0; nt < 8; nt++)
#pragma unroll
            for (int j = 0; j < 4; j++) acc[mt][nt][j] = 0.0f;

    // ---- prologue: stages 0..2 ----
#pragma unroll
    for (int p = 0; p < 3; p++) {
        const uint32_t aB = smem_base + p * (STAGE_H * 2) + dOff;
        const uint32_t bB = aB + (uint32_t)(TILE_H * 2);
        const int k0 = p * 32;
#pragma unroll
        for (int i = 0; i < 2; i++) {
            cpa_cg(aB + i * 64 * SSTRH * 2, aG + (size_t)i * 64 * H1 + k0);
            cpa_ca(bB + i * 64 * SSTRH * 2, bG + (size_t)i * 64 * H1 + k0);
        }
        asm volatile("cp.async.commit_group;");
    }

    // ---- main loop: 32 slabs ----
    for (int s = 0; s < 32; s++) {
        const int stg = s & 3;
        asm volatile("cp.async.wait_group 2;");
        __syncthreads();

        if (s + 3 < 32) {
            const int pst = (s + 3) & 3;
            const uint32_t aB = smem_base + pst * (STAGE_H * 2) + dOff;
            const uint32_t bB = aB + (uint32_t)(TILE_H * 2);
            const int k0 = (s + 3) * 32;
#pragma unroll
            for (int i = 0; i < 2; i++) {
                cpa_cg(aB + i * 64 * SSTRH * 2, aG + (size_t)i * 64 * H1 + k0);
                cpa_ca(bB + i * 64 * SSTRH * 2, bG + (size_t)i * 64 * H1 + k0);
            }
        }
        asm volatile("cp.async.commit_group;");

        // ---- compute stage stg: 2 k-steps of m16n8k16 ----
        {
            const __half* Ab = smh + stg * STAGE_H;
            const __half* Bb = Ab + TILE_H;
#pragma unroll
            for (int ks = 0; ks < 2; ks++) {
                const int kc = ks * 16 + 2 * t;
                uint32_t af[2][4];
#pragma unroll
                for (int mt = 0; mt < 2; mt++) {
                    const __half* ap = Ab + (wm + mt * 16 + g) * SSTRH + kc;
                    af[mt][0] = *(const uint32_t*)(ap);
                    af[mt][1] = *(const uint32_t*)(ap + 8 * SSTRH);
                    af[mt][2] = *(const uint32_t*)(ap + 8);
                    af[mt][3] = *(const uint32_t*)(ap + 8 * SSTRH + 8);
                }
#pragma unroll
                for (int nt = 0; nt < 8; nt++) {
                    const __half* bp = Bb + (wn + nt * 8 + g) * SSTRH + kc;
                    uint32_t bf[2];
                    bf[0] = *(const uint32_t*)(bp);
                    bf[1] = *(const uint32_t*)(bp + 8);
                    mma16(acc[0][nt], af[0], bf);
                    mma16(acc[1][nt], af[1], bf);
                }
            }
        }
    }

    // ---- epilogue: relu + partial layer-3 dots ----
    if (tid < 128) ws[0][tid] = w0g[tid];
    else           ws[1][tid - 128] = w1g[tid - 128];
    __syncthreads();

    float u[4][2];
#pragma unroll
    for (int q = 0; q < 4; q++) { u[q][0] = 0.0f; u[q][1] = 0.0f; }

#pragma unroll
    for (int nt = 0; nt < 8; nt++) {
        const int col = wn + nt * 8 + t * 2;
        const float2 bb = *(const float2*)&bsrc[col];
        const float wa0 = ws[0][col], wa1 = ws[0][col + 1];
        const float wb0 = ws[1][col], wb1 = ws[1][col + 1];
#pragma unroll
        for (int q = 0; q < 4; q++) {
            const int mt = q >> 1, h = q & 1;
            const float v0 = fmaxf(acc[mt][nt][h * 2 + 0] + bb.x, 0.0f);
            const float v1 = fmaxf(acc[mt][nt][h * 2 + 1] + bb.y, 0.0f);
            u[q][0] = fmaf(v0, wa0, fmaf(v1, wa1, u[q][0]));
            u[q][1] = fmaf(v0, wb0, fmaf(v1, wb1, u[q][1]));
        }
    }

#pragma unroll
    for (int q = 0; q < 4; q++)
#pragma unroll
        for (int c = 0; c < 2; c++) {
            u[q][c] += __shfl_xor_sync(0xFFFFFFFFu, u[q][c], 1);
            u[q][c] += __shfl_xor_sync(0xFFFFFFFFu, u[q][c], 2);
        }

    if (t == 0) {
#pragma unroll
        for (int q = 0; q < 4; q++) {
            const int row = wm + (q >> 1) * 16 + (q & 1) * 8 + g;
            sred[half][row][0] = u[q][0];
            sred[half][row][1] = u[q][1];
        }
    }
    __syncthreads();

    {
        const int row = tid >> 1;
        const int c   = tid & 1;
        const float sum = sred[0][row][c] + sred[1][row][c];
        const int nb4 = blockIdx.x & 3;
        g_part[(size_t)(m0 + row) * 16 + pair * 8 + nb4 * 2 + c] = sum;
    }
}

// ---------------------------------------------------------------------------
// Kernel 3: per-row partial sum + sigmoid + CBF epilogue. grid 128, block 256.
// ---------------------------------------------------------------------------
__global__ __launch_bounds__(256) void k3_final(
    const float* __restrict__ x,
    const float* __restrict__ mean_, const float* __restrict__ stdv,
    const float* __restrict__ b31,   const float* __restrict__ bobs2,
    float* __restrict__ out)
{
    const int row = blockIdx.x * 256 + threadIdx.x;

    const float* pp = &g_part[(size_t)row * 16];
    float4 pa = *(const float4*)&pp[0];
    float4 pb = *(const float4*)&pp[4];
    float4 pc = *(const float4*)&pp[8];
    float4 pd = *(const float4*)&pp[12];

    const float x31_0 = pa.x + pa.z + pb.x + pb.z + b31[0];
    const float x31_1 = pa.y + pa.w + pb.y + pb.w + b31[1];
    const float t0    = pc.x + pc.z + pd.x + pd.z + bobs2[0];
    const float t1    = pc.y + pc.w + pd.y + pd.w + bobs2[1];
    const float p0 = 4.0f / (1.0f + expf(-t0));
    const float p1 = 4.0f / (1.0f + expf(-t1));

    const float* xr = x + (size_t)row * NUM_IN;
    float x0v[NUM_IN];
#pragma unroll
    for (int c = 2; c < NUM_IN; c++) x0v[c] = fmaf(xr[c], stdv[c], mean_[c]);

    const float theta = x0v[2];
    const float v     = x0v[3];
    const float st = sinf(theta), ct = cosf(theta);
    const float ox = x0v[4], oy = x0v[5], oth = x0v[6], ov = x0v[7];
    const float dx = -ox, dy = -oy;
    const float ost = sinf(oth), oct = cosf(oth);
    const float R2 = 0.45f * 0.45f;

    const float barrier = dx * dx + dy * dy - R2;
    const float bdot    = 2.0f * dx * (v * ct - ov * oct)
                        + 2.0f * dy * (v * st - ov * ost);
    const float Lf2b    = 2.0f * (v * v + ov * ov
                        - 2.0f * v * ov * cosf(theta + oth));
    const float Gu1 = -2.0f * dx * v * st + 2.0f * dy * v * ct;
    const float Gu2 =  2.0f * dx * ct + 2.0f * dy * st;

    const float psum  = p0 + p1;
    const float pprod = p0 * p1;

    float o[14];
    o[0]  = x31_0;
    o[1]  = x31_1;
    o[2]  = -Gu1;
    o[3]  = -Gu2;
    o[10] = Lf2b + psum * bdot + pprod * barrier;

    const float sLf2b = 2.0f * v * v;
#pragma unroll
    for (int j = 0; j < 3; j++) {
        const float sdx = -x0v[8 + 4 * j];
        const float sdy = -x0v[9 + 4 * j];
        const float sb    = sdx * sdx + sdy * sdy - R2;
        const float sbdot = 2.0f * sdx * v * ct + 2.0f * sdy * v * st;
        const float sGu1  = -2.0f * sdx * v * st + 2.0f * sdy * v * ct;
        const float sGu2  =  2.0f * sdx * ct + 2.0f * sdy * st;
        o[4 + 2 * j] = -sGu1;
        o[5 + 2 * j] = -sGu2;
        o[11 + j]    = sLf2b + psum * sbdot + pprod * sb;
    }

    float* op = out + (size_t)row * 14;
#pragma unroll
    for (int i = 0; i < 14; i++) op[i] = o[i];
}

// ---------------------------------------------------------------------------
// Launch
// ---------------------------------------------------------------------------
extern "C" void kernel_launch(void* const* d_in, const int* in_sizes, int n_in,
                              void* d_out, int out_size)
{
    const float* x      = (const float*)d_in[0];
    const float* mean_  = (const float*)d_in[2];
    const float* stdv   = (const float*)d_in[3];
    const float* W1     = (const float*)d_in[4];
    const float* b1     = (const float*)d_in[5];
    const float* W21    = (const float*)d_in[6];
    const float* b21    = (const float*)d_in[7];
    const float* W31    = (const float*)d_in[8];
    const float* b31    = (const float*)d_in[9];
    const float* Wobs1  = (const float*)d_in[10];
    const float* bobs1  = (const float*)d_in[11];
    const float* Wobs2  = (const float*)d_in[12];
    const float* bobs2  = (const float*)d_in[13];
    float* out = (float*)d_out;

    cudaFuncSetAttribute(k2_mma, cudaFuncAttributeMaxDynamicSharedMemorySize,
                         K2_SMEM_BYTES);

    k0_convert<<<1024, 256>>>(W21, Wobs1);
    k1_layer1<<<dim3(2, B_ROWS / 64), 256>>>(x, W1, b1);
    k2_mma<<<dim3(8, B_ROWS / 128), 256, K2_SMEM_BYTES>>>(b21, bobs1, W31, Wobs2);
    k3_final<<<B_ROWS / 256, 256>>>(x, mean_, stdv, b31, bobs2, out);
}

// round 7
// speedup vs baseline: 5.4467x; 1.0344x over previous
#include <cuda_runtime.h>
#include <cuda_fp16.h>
#include <math.h>
#include <stdint.h>

// ---------------------------------------------------------------------------
// LiveNet fused forward (sm_100 plain target; fp16 mma.sync m16n8k16).
//   K0a: convert [W21;Wobs1] fp32 -> fp16 g_wh              [1024,1024]
//   K0b: convert x -> g_xh [32768,32] fp16 (K padded 20->32), W1 -> g_w1h
//   K1 : h = relu(x_pad @ W1p^T + b1) via mma -> g_h (fp16) [32768,1024]
//   K2 : fp16 GEMM h @ g_wh^T, fused relu + layer-3 partial dots -> g_part
//   K3 : sum partials, sigmoid, CBF epilogue -> out [32768,14]
// ---------------------------------------------------------------------------

#define B_ROWS 32768
#define NUM_IN 20
#define H1     1024
#define KPAD   32

__device__ __half g_h  [(size_t)B_ROWS * H1];
__device__ __half g_wh [(size_t)1024 * H1];
__device__ __half g_xh [(size_t)B_ROWS * KPAD];
__device__ __half g_w1h[(size_t)1024 * KPAD];
__device__ float  g_part[(size_t)B_ROWS * 16];

// ---------------------------------------------------------------------------
// Kernel 0a: layer-2 weight conversion. grid 1024, block 256.
// ---------------------------------------------------------------------------
__global__ __launch_bounds__(256) void k0_convert(
    const float* __restrict__ W21, const float* __restrict__ Wobs1)
{
    const size_t i4 = ((size_t)blockIdx.x * 256 + threadIdx.x) * 4;
    const size_t half_total = (size_t)512 * H1;
    const float* src = (i4 < half_total) ? (W21 + i4) : (Wobs1 + (i4 - half_total));
    float4 v = *(const float4*)src;
    __half2* dst = (__half2*)&g_wh[i4];
    dst[0] = __floats2half2_rn(v.x, v.y);
    dst[1] = __floats2half2_rn(v.z, v.w);
}

// ---------------------------------------------------------------------------
// Kernel 0b: x and W1 -> fp16, K padded to 32. One row per thread.
// grid 132, block 256 (32768 x-rows + 1024 W1-rows).
// ---------------------------------------------------------------------------
__global__ __launch_bounds__(256) void k0b_convert(
    const float* __restrict__ x, const float* __restrict__ W1)
{
    const int idx = blockIdx.x * 256 + threadIdx.x;
    const float* src;
    __half* dst;
    if (idx < B_ROWS) {
        src = x + (size_t)idx * NUM_IN;
        dst = &g_xh[(size_t)idx * KPAD];
    } else if (idx < B_ROWS + 1024) {
        src = W1 + (size_t)(idx - B_ROWS) * NUM_IN;
        dst = &g_w1h[(size_t)(idx - B_ROWS) * KPAD];
    } else {
        return;
    }
    __half2* d2 = (__half2*)dst;
#pragma unroll
    for (int j = 0; j < 10; j++) d2[j] = __floats2half2_rn(src[2 * j], src[2 * j + 1]);
#pragma unroll
    for (int j = 10; j < 16; j++) d2[j] = __floats2half2_rn(0.0f, 0.0f);
}

// ---------------------------------------------------------------------------
// shared mma helper
// ---------------------------------------------------------------------------
__device__ __forceinline__ void mma16(float* c, const uint32_t* a, const uint32_t* b) {
    asm volatile(
        "mma.sync.aligned.m16n8k16.row.col.f32.f16.f16.f32 "
        "{%0,%1,%2,%3}, {%4,%5,%6,%7}, {%8,%9}, {%0,%1,%2,%3};"
        : "+f"(c[0]), "+f"(c[1]), "+f"(c[2]), "+f"(c[3])
        : "r"(a[0]), "r"(a[1]), "r"(a[2]), "r"(a[3]), "r"(b[0]), "r"(b[1]));
}

// ---------------------------------------------------------------------------
// Kernel 1: layer-1 via mma. BM=128, BN=128, K=32 (single slab).
// grid (8, 256), block 256 (8 warps, warp tile 32x64).
// ---------------------------------------------------------------------------
#define K1_SSTR 40   // smem row stride in halfs (32 + 8 pad)

__global__ __launch_bounds__(256) void k1_mma(const float* __restrict__ b1)
{
    __shared__ __half xa[128 * K1_SSTR];
    __shared__ __half wb[128 * K1_SSTR];
    __shared__ float  bs[128];

    const int tid  = threadIdx.x;
    const int wid  = tid >> 5;
    const int lane = tid & 31;
    const int g    = lane >> 2;
    const int t    = lane & 3;
    const int wm   = (wid & 3) * 32;
    const int wn   = (wid >> 2) * 64;

    const int m0 = blockIdx.y * 128;
    const int n0 = blockIdx.x * 128;

    // load tiles: 128 rows x 32 halfs each = 512 x 16B chunks per tile
#pragma unroll
    for (int i = 0; i < 2; i++) {
        const int id  = tid + i * 256;
        const int row = id >> 2;
        const int q   = id & 3;
        *(uint4*)&xa[row * K1_SSTR + q * 8] =
            *(const uint4*)&g_xh[(size_t)(m0 + row) * KPAD + q * 8];
        *(uint4*)&wb[row * K1_SSTR + q * 8] =
            *(const uint4*)&g_w1h[(size_t)(n0 + row) * KPAD + q * 8];
    }
    if (tid < 128) bs[tid] = b1[n0 + tid];
    __syncthreads();

    float acc[2][8][4];
#pragma unroll
    for (int mt = 0; mt < 2; mt++)
#pragma unroll
        for (int nt = 0; nt < 8; nt++)
#pragma unroll
            for (int j = 0; j < 4; j++) acc[mt][nt][j] = 0.0f;

#pragma unroll
    for (int ks = 0; ks < 2; ks++) {
        const int kc = ks * 16 + 2 * t;
        uint32_t af[2][4];
#pragma unroll
        for (int mt = 0; mt < 2; mt++) {
            const __half* ap = xa + (wm + mt * 16 + g) * K1_SSTR + kc;
            af[mt][0] = *(const uint32_t*)(ap);
            af[mt][1] = *(const uint32_t*)(ap + 8 * K1_SSTR);
            af[mt][2] = *(const uint32_t*)(ap + 8);
            af[mt][3] = *(const uint32_t*)(ap + 8 * K1_SSTR + 8);
        }
#pragma unroll
        for (int nt = 0; nt < 8; nt++) {
            const __half* bp = wb + (wn + nt * 8 + g) * K1_SSTR + kc;
            uint32_t bf[2];
            bf[0] = *(const uint32_t*)(bp);
            bf[1] = *(const uint32_t*)(bp + 8);
            mma16(acc[0][nt], af[0], bf);
            mma16(acc[1][nt], af[1], bf);
        }
    }

    // epilogue: bias + relu -> half2 stores
#pragma unroll
    for (int nt = 0; nt < 8; nt++) {
        const int col = wn + nt * 8 + t * 2;
        const float b0 = bs[col], b1v = bs[col + 1];
#pragma unroll
        for (int q = 0; q < 4; q++) {
            const int mt = q >> 1, h = q & 1;
            const int row = m0 + wm + mt * 16 + h * 8 + g;
            const float v0 = fmaxf(acc[mt][nt][h * 2 + 0] + b0, 0.0f);
            const float v1 = fmaxf(acc[mt][nt][h * 2 + 1] + b1v, 0.0f);
            *(__half2*)&g_h[(size_t)row * H1 + n0 + col] = __floats2half2_rn(v0, v1);
        }
    }
}

// ---------------------------------------------------------------------------
// Kernel 2: fp16 mma.sync GEMM. BM=128, BN=128, BK=32, 4-stage cp.async.
// grid (8, 256), block 256. Epilogue: relu + layer-3 partial dots.
// ---------------------------------------------------------------------------
#define SSTRH    40
#define TILE_H   (128 * SSTRH)
#define STAGE_H  (2 * TILE_H)
#define K2_SMEM_BYTES (4 * STAGE_H * 2)

__device__ __forceinline__ void cpa_cg(uint32_t d, const __half* s) {
    asm volatile("cp.async.cg.shared.global [%0], [%1], 16;" :: "r"(d), "l"(s));
}
__device__ __forceinline__ void cpa_ca(uint32_t d, const __half* s) {
    asm volatile("cp.async.ca.shared.global [%0], [%1], 16;" :: "r"(d), "l"(s));
}

__global__ __launch_bounds__(256, 2) void k2_mma(
    const float* __restrict__ b21,  const float* __restrict__ bobs1,
    const float* __restrict__ W31,  const float* __restrict__ Wobs2)
{
    extern __shared__ __half smh[];
    __shared__ float ws[2][128];
    __shared__ float sred[2][128][2];

    const int tid  = threadIdx.x;
    const int wid  = tid >> 5;
    const int lane = tid & 31;
    const int g    = lane >> 2;
    const int t    = lane & 3;
    const int wm   = (wid & 3) * 32;
    const int wn   = (wid >> 2) * 64;
    const int half = wid >> 2;

    const int m0 = blockIdx.y * 128;
    const int n0 = blockIdx.x * 128;
    const int pair = (n0 >= 512);

    const float* bsrc = pair ? (bobs1 + (n0 - 512)) : (b21 + n0);
    const float* w0g  = pair ? (Wobs2 + (n0 - 512)) : (W31 + n0);
    const float* w1g  = pair ? (Wobs2 + 512 + (n0 - 512)) : (W31 + 512 + n0);

    const int lm = tid >> 2;
    const int lq = tid & 3;
    const __half* aG = &g_h [(size_t)(m0 + lm) * H1 + lq * 8];
    const __half* bG = &g_wh[(size_t)(n0 + lm) * H1 + lq * 8];

    uint32_t smem_base;
    asm("{ .reg .u64 t; cvta.to.shared.u64 t, %1; cvt.u32.u64 %0, t; }"
        : "=r"(smem_base) : "l"(smh));
    const uint32_t dOff = (uint32_t)(lm * SSTRH * 2 + lq * 16);

    float acc[2][8][4];
#pragma unroll
    for (int mt = 0; mt < 2; mt++)
#pragma unroll
        for (int nt = 0; nt < 8; nt++)
#pragma unroll
            for (int j = 0; j < 4; j++) acc[mt][nt][j] = 0.0f;

#pragma unroll
    for (int p = 0; p < 3; p++) {
        const uint32_t aB = smem_base + p * (STAGE_H * 2) + dOff;
        const uint32_t bB = aB + (uint32_t)(TILE_H * 2);
        const int k0 = p * 32;
#pragma unroll
        for (int i = 0; i < 2; i++) {
            cpa_cg(aB + i * 64 * SSTRH * 2, aG + (size_t)i * 64 * H1 + k0);
            cpa_ca(bB + i * 64 * SSTRH * 2, bG + (size_t)i * 64 * H1 + k0);
        }
        asm volatile("cp.async.commit_group;");
    }

    for (int s = 0; s < 32; s++) {
        const int stg = s & 3;
        asm volatile("cp.async.wait_group 2;");
        __syncthreads();

        if (s + 3 < 32) {
            const int pst = (s + 3) & 3;
            const uint32_t aB = smem_base + pst * (STAGE_H * 2) + dOff;
            const uint32_t bB = aB + (uint32_t)(TILE_H * 2);
            const int k0 = (s + 3) * 32;
#pragma unroll
            for (int i = 0; i < 2; i++) {
                cpa_cg(aB + i * 64 * SSTRH * 2, aG + (size_t)i * 64 * H1 + k0);
                cpa_ca(bB + i * 64 * SSTRH * 2, bG + (size_t)i * 64 * H1 + k0);
            }
        }
        asm volatile("cp.async.commit_group;");

        {
            const __half* Ab = smh + stg * STAGE_H;
            const __half* Bb = Ab + TILE_H;
#pragma unroll
            for (int ks = 0; ks < 2; ks++) {
                const int kc = ks * 16 + 2 * t;
                uint32_t af[2][4];
#pragma unroll
                for (int mt = 0; mt < 2; mt++) {
                    const __half* ap = Ab + (wm + mt * 16 + g) * SSTRH + kc;
                    af[mt][0] = *(const uint32_t*)(ap);
                    af[mt][1] = *(const uint32_t*)(ap + 8 * SSTRH);
                    af[mt][2] = *(const uint32_t*)(ap + 8);
                    af[mt][3] = *(const uint32_t*)(ap + 8 * SSTRH + 8);
                }
#pragma unroll
                for (int nt = 0; nt < 8; nt++) {
                    const __half* bp = Bb + (wn + nt * 8 + g) * SSTRH + kc;
                    uint32_t bf[2];
                    bf[0] = *(const uint32_t*)(bp);
                    bf[1] = *(const uint32_t*)(bp + 8);
                    mma16(acc[0][nt], af[0], bf);
                    mma16(acc[1][nt], af[1], bf);
                }
            }
        }
    }

    // ---- epilogue: relu + partial layer-3 dots ----
    if (tid < 128) ws[0][tid] = w0g[tid];
    else           ws[1][tid - 128] = w1g[tid - 128];
    __syncthreads();

    float u[4][2];
#pragma unroll
    for (int q = 0; q < 4; q++) { u[q][0] = 0.0f; u[q][1] = 0.0f; }

#pragma unroll
    for (int nt = 0; nt < 8; nt++) {
        const int col = wn + nt * 8 + t * 2;
        const float2 bb = *(const float2*)&bsrc[col];
        const float wa0 = ws[0][col], wa1 = ws[0][col + 1];
        const float wb0 = ws[1][col], wb1 = ws[1][col + 1];
#pragma unroll
        for (int q = 0; q < 4; q++) {
            const int mt = q >> 1, h = q & 1;
            const float v0 = fmaxf(acc[mt][nt][h * 2 + 0] + bb.x, 0.0f);
            const float v1 = fmaxf(acc[mt][nt][h * 2 + 1] + bb.y, 0.0f);
            u[q][0] = fmaf(v0, wa0, fmaf(v1, wa1, u[q][0]));
            u[q][1] = fmaf(v0, wb0, fmaf(v1, wb1, u[q][1]));
        }
    }

#pragma unroll
    for (int q = 0; q < 4; q++)
#pragma unroll
        for (int c = 0; c < 2; c++) {
            u[q][c] += __shfl_xor_sync(0xFFFFFFFFu, u[q][c], 1);
            u[q][c] += __shfl_xor_sync(0xFFFFFFFFu, u[q][c], 2);
        }

    if (t == 0) {
#pragma unroll
        for (int q = 0; q < 4; q++) {
            const int row = wm + (q >> 1) * 16 + (q & 1) * 8 + g;
            sred[half][row][0] = u[q][0];
            sred[half][row][1] = u[q][1];
        }
    }
    __syncthreads();

    {
        const int row = tid >> 1;
        const int c   = tid & 1;
        const float sum = sred[0][row][c] + sred[1][row][c];
        const int nb4 = blockIdx.x & 3;
        g_part[(size_t)(m0 + row) * 16 + pair * 8 + nb4 * 2 + c] = sum;
    }
}

// ---------------------------------------------------------------------------
// Kernel 3: per-row partial sum + sigmoid + CBF epilogue. grid 128, block 256.
// ---------------------------------------------------------------------------
__global__ __launch_bounds__(256) void k3_final(
    const float* __restrict__ x,
    const float* __restrict__ mean_, const float* __restrict__ stdv,
    const float* __restrict__ b31,   const float* __restrict__ bobs2,
    float* __restrict__ out)
{
    const int row = blockIdx.x * 256 + threadIdx.x;

    const float* pp = &g_part[(size_t)row * 16];
    float4 pa = *(const float4*)&pp[0];
    float4 pb = *(const float4*)&pp[4];
    float4 pc = *(const float4*)&pp[8];
    float4 pd = *(const float4*)&pp[12];

    const float x31_0 = pa.x + pa.z + pb.x + pb.z + b31[0];
    const float x31_1 = pa.y + pa.w + pb.y + pb.w + b31[1];
    const float t0    = pc.x + pc.z + pd.x + pd.z + bobs2[0];
    const float t1    = pc.y + pc.w + pd.y + pd.w + bobs2[1];
    const float p0 = 4.0f / (1.0f + expf(-t0));
    const float p1 = 4.0f / (1.0f + expf(-t1));

    const float* xr = x + (size_t)row * NUM_IN;
    float x0v[NUM_IN];
#pragma unroll
    for (int c = 2; c < NUM_IN; c++) x0v[c] = fmaf(xr[c], stdv[c], mean_[c]);

    const float theta = x0v[2];
    const float v     = x0v[3];
    const float st = sinf(theta), ct = cosf(theta);
    const float ox = x0v[4], oy = x0v[5], oth = x0v[6], ov = x0v[7];
    const float dx = -ox, dy = -oy;
    const float ost = sinf(oth), oct = cosf(oth);
    const float R2 = 0.45f * 0.45f;

    const float barrier = dx * dx + dy * dy - R2;
    const float bdot    = 2.0f * dx * (v * ct - ov * oct)
                        + 2.0f * dy * (v * st - ov * ost);
    const float Lf2b    = 2.0f * (v * v + ov * ov
                        - 2.0f * v * ov * cosf(theta + oth));
    const float Gu1 = -2.0f * dx * v * st + 2.0f * dy * v * ct;
    const float Gu2 =  2.0f * dx * ct + 2.0f * dy * st;

    const float psum  = p0 + p1;
    const float pprod = p0 * p1;

    float o[14];
    o[0]  = x31_0;
    o[1]  = x31_1;
    o[2]  = -Gu1;
    o[3]  = -Gu2;
    o[10] = Lf2b + psum * bdot + pprod * barrier;

    const float sLf2b = 2.0f * v * v;
#pragma unroll
    for (int j = 0; j < 3; j++) {
        const float sdx = -x0v[8 + 4 * j];
        const float sdy = -x0v[9 + 4 * j];
        const float sb    = sdx * sdx + sdy * sdy - R2;
        const float sbdot = 2.0f * sdx * v * ct + 2.0f * sdy * v * st;
        const float sGu1  = -2.0f * sdx * v * st + 2.0f * sdy * v * ct;
        const float sGu2  =  2.0f * sdx * ct + 2.0f * sdy * st;
        o[4 + 2 * j] = -sGu1;
        o[5 + 2 * j] = -sGu2;
        o[11 + j]    = sLf2b + psum * sbdot + pprod * sb;
    }

    float* op = out + (size_t)row * 14;
#pragma unroll
    for (int i = 0; i < 14; i++) op[i] = o[i];
}

// ---------------------------------------------------------------------------
// Launch
// ---------------------------------------------------------------------------
extern "C" void kernel_launch(void* const* d_in, const int* in_sizes, int n_in,
                              void* d_out, int out_size)
{
    const float* x      = (const float*)d_in[0];
    const float* mean_  = (const float*)d_in[2];
    const float* stdv   = (const float*)d_in[3];
    const float* W1     = (const float*)d_in[4];
    const float* b1     = (const float*)d_in[5];
    const float* W21    = (const float*)d_in[6];
    const float* b21    = (const float*)d_in[7];
    const float* W31    = (const float*)d_in[8];
    const float* b31    = (const float*)d_in[9];
    const float* Wobs1  = (const float*)d_in[10];
    const float* bobs1  = (const float*)d_in[11];
    const float* Wobs2  = (const float*)d_in[12];
    const float* bobs2  = (const float*)d_in[13];
    float* out = (float*)d_out;

    cudaFuncSetAttribute(k2_mma, cudaFuncAttributeMaxDynamicSharedMemorySize,
                         K2_SMEM_BYTES);

    k0_convert<<<1024, 256>>>(W21, Wobs1);
    k0b_convert<<<(B_ROWS + 1024 + 255) / 256, 256>>>(x, W1);
    k1_mma<<<dim3(8, B_ROWS / 128), 256>>>(b1);
    k2_mma<<<dim3(8, B_ROWS / 128), 256, K2_SMEM_BYTES>>>(b21, bobs1, W31, Wobs2);
    k3_final<<<B_ROWS / 256, 256>>>(x, mean_, stdv, b31, bobs2, out);
}

// round 8
// speedup vs baseline: 6.0736x; 1.1151x over previous
#include <cuda_runtime.h>
#include <cuda_fp16.h>
#include <math.h>
#include <stdint.h>

// ---------------------------------------------------------------------------
// LiveNet fused forward (sm_100 plain target; fp16 mma.sync + ldmatrix).
//   K0a: convert [W21;Wobs1] fp32 -> fp16 g_wh              [1024,1024]
//   K0b: convert x -> g_xh [32768,32] fp16 (pad 20->32), W1 -> g_w1h
//   K1 : h = relu(x_pad @ W1p^T + b1) via mma -> g_h (fp16) [32768,1024]
//   K2 : fp16 GEMM h @ g_wh^T, fused relu + layer-3 partial dots -> g_part
//   K3 : sum partials, sigmoid, CBF epilogue -> out [32768,14]
// ---------------------------------------------------------------------------

#define B_ROWS 32768
#define NUM_IN 20
#define H1     1024
#define KPAD   32

__device__ __half g_h  [(size_t)B_ROWS * H1];
__device__ __half g_wh [(size_t)1024 * H1];
__device__ __half g_xh [(size_t)B_ROWS * KPAD];
__device__ __half g_w1h[(size_t)1024 * KPAD];
__device__ float  g_part[(size_t)B_ROWS * 16];

// ---------------------------------------------------------------------------
// Kernel 0a: layer-2 weight conversion. grid 1024, block 256.
// ---------------------------------------------------------------------------
__global__ __launch_bounds__(256) void k0_convert(
    const float* __restrict__ W21, const float* __restrict__ Wobs1)
{
    const size_t i4 = ((size_t)blockIdx.x * 256 + threadIdx.x) * 4;
    const size_t half_total = (size_t)512 * H1;
    const float* src = (i4 < half_total) ? (W21 + i4) : (Wobs1 + (i4 - half_total));
    float4 v = *(const float4*)src;
    __half2* dst = (__half2*)&g_wh[i4];
    dst[0] = __floats2half2_rn(v.x, v.y);
    dst[1] = __floats2half2_rn(v.z, v.w);
}

// ---------------------------------------------------------------------------
// Kernel 0b: x and W1 -> fp16, K padded to 32. One row per thread.
// ---------------------------------------------------------------------------
__global__ __launch_bounds__(256) void k0b_convert(
    const float* __restrict__ x, const float* __restrict__ W1)
{
    const int idx = blockIdx.x * 256 + threadIdx.x;
    const float* src;
    __half* dst;
    if (idx < B_ROWS) {
        src = x + (size_t)idx * NUM_IN;
        dst = &g_xh[(size_t)idx * KPAD];
    } else if (idx < B_ROWS + 1024) {
        src = W1 + (size_t)(idx - B_ROWS) * NUM_IN;
        dst = &g_w1h[(size_t)(idx - B_ROWS) * KPAD];
    } else {
        return;
    }
    __half2* d2 = (__half2*)dst;
#pragma unroll
    for (int j = 0; j < 10; j++) d2[j] = __floats2half2_rn(src[2 * j], src[2 * j + 1]);
#pragma unroll
    for (int j = 10; j < 16; j++) d2[j] = __floats2half2_rn(0.0f, 0.0f);
}

// ---------------------------------------------------------------------------
// helpers
// ---------------------------------------------------------------------------
__device__ __forceinline__ void mma16(float* c, const uint32_t* a, const uint32_t* b) {
    asm volatile(
        "mma.sync.aligned.m16n8k16.row.col.f32.f16.f16.f32 "
        "{%0,%1,%2,%3}, {%4,%5,%6,%7}, {%8,%9}, {%0,%1,%2,%3};"
        : "+f"(c[0]), "+f"(c[1]), "+f"(c[2]), "+f"(c[3])
        : "r"(a[0]), "r"(a[1]), "r"(a[2]), "r"(a[3]), "r"(b[0]), "r"(b[1]));
}

__device__ __forceinline__ void ldmx4(uint32_t* r, uint32_t addr) {
    asm volatile("ldmatrix.sync.aligned.m8n8.x4.shared.b16 {%0,%1,%2,%3}, [%4];"
                 : "=r"(r[0]), "=r"(r[1]), "=r"(r[2]), "=r"(r[3]) : "r"(addr));
}

// ---------------------------------------------------------------------------
// Kernel 1: layer-1 via mma. BM=128, BN=128, K=32 (single slab).
// grid (8, 256), block 256 (8 warps, warp tile 32x64).
// ---------------------------------------------------------------------------
#define K1_SSTR 40   // smem row stride in halfs (32 + 8 pad)

__global__ __launch_bounds__(256) void k1_mma(const float* __restrict__ b1)
{
    __shared__ __half xa[128 * K1_SSTR];
    __shared__ __half wb[128 * K1_SSTR];
    __shared__ float  bs[128];

    const int tid  = threadIdx.x;
    const int wid  = tid >> 5;
    const int lane = tid & 31;
    const int g    = lane >> 2;
    const int t    = lane & 3;
    const int wm   = (wid & 3) * 32;
    const int wn   = (wid >> 2) * 64;

    const int m0 = blockIdx.y * 128;
    const int n0 = blockIdx.x * 128;

#pragma unroll
    for (int i = 0; i < 2; i++) {
        const int id  = tid + i * 256;
        const int row = id >> 2;
        const int q   = id & 3;
        *(uint4*)&xa[row * K1_SSTR + q * 8] =
            *(const uint4*)&g_xh[(size_t)(m0 + row) * KPAD + q * 8];
        *(uint4*)&wb[row * K1_SSTR + q * 8] =
            *(const uint4*)&g_w1h[(size_t)(n0 + row) * KPAD + q * 8];
    }
    if (tid < 128) bs[tid] = b1[n0 + tid];
    __syncthreads();

    float acc[2][8][4];
#pragma unroll
    for (int mt = 0; mt < 2; mt++)
#pragma unroll
        for (int nt = 0; nt < 8; nt++)
#pragma unroll
            for (int j = 0; j < 4; j++) acc[mt][nt][j] = 0.0f;

#pragma unroll
    for (int ks = 0; ks < 2; ks++) {
        const int kc = ks * 16 + 2 * t;
        uint32_t af[2][4];
#pragma unroll
        for (int mt = 0; mt < 2; mt++) {
            const __half* ap = xa + (wm + mt * 16 + g) * K1_SSTR + kc;
            af[mt][0] = *(const uint32_t*)(ap);
            af[mt][1] = *(const uint32_t*)(ap + 8 * K1_SSTR);
            af[mt][2] = *(const uint32_t*)(ap + 8);
            af[mt][3] = *(const uint32_t*)(ap + 8 * K1_SSTR + 8);
        }
#pragma unroll
        for (int nt = 0; nt < 8; nt++) {
            const __half* bp = wb + (wn + nt * 8 + g) * K1_SSTR + kc;
            uint32_t bf[2];
            bf[0] = *(const uint32_t*)(bp);
            bf[1] = *(const uint32_t*)(bp + 8);
            mma16(acc[0][nt], af[0], bf);
            mma16(acc[1][nt], af[1], bf);
        }
    }

#pragma unroll
    for (int nt = 0; nt < 8; nt++) {
        const int col = wn + nt * 8 + t * 2;
        const float b0 = bs[col], b1v = bs[col + 1];
#pragma unroll
        for (int q = 0; q < 4; q++) {
            const int mt = q >> 1, h = q & 1;
            const int row = m0 + wm + mt * 16 + h * 8 + g;
            const float v0 = fmaxf(acc[mt][nt][h * 2 + 0] + b0, 0.0f);
            const float v1 = fmaxf(acc[mt][nt][h * 2 + 1] + b1v, 0.0f);
            *(__half2*)&g_h[(size_t)row * H1 + n0 + col] = __floats2half2_rn(v0, v1);
        }
    }
}

// ---------------------------------------------------------------------------
// Kernel 2: fp16 mma.sync GEMM with ldmatrix fragments.
// BM=128, BN=128, BK=32, 4-stage cp.async. grid (8, 256), block 256.
// ---------------------------------------------------------------------------
#define SSTRH    40
#define TILE_H   (128 * SSTRH)
#define STAGE_H  (2 * TILE_H)
#define STAGE_B  (STAGE_H * 2)          // stage bytes
#define TILE_B   (TILE_H * 2)           // tile bytes
#define K2_SMEM_BYTES (4 * STAGE_B)

__device__ __forceinline__ void cpa_cg(uint32_t d, const __half* s) {
    asm volatile("cp.async.cg.shared.global [%0], [%1], 16;" :: "r"(d), "l"(s));
}
__device__ __forceinline__ void cpa_ca(uint32_t d, const __half* s) {
    asm volatile("cp.async.ca.shared.global [%0], [%1], 16;" :: "r"(d), "l"(s));
}

__global__ __launch_bounds__(256, 2) void k2_mma(
    const float* __restrict__ b21,  const float* __restrict__ bobs1,
    const float* __restrict__ W31,  const float* __restrict__ Wobs2)
{
    extern __shared__ __half smh[];
    __shared__ float ws[2][128];
    __shared__ float sred[2][128][2];

    const int tid  = threadIdx.x;
    const int wid  = tid >> 5;
    const int lane = tid & 31;
    const int g    = lane >> 2;
    const int t    = lane & 3;
    const int wm   = (wid & 3) * 32;
    const int wn   = (wid >> 2) * 64;
    const int half = wid >> 2;

    const int m0 = blockIdx.y * 128;
    const int n0 = blockIdx.x * 128;
    const int pair = (n0 >= 512);

    const float* bsrc = pair ? (bobs1 + (n0 - 512)) : (b21 + n0);
    const float* w0g  = pair ? (Wobs2 + (n0 - 512)) : (W31 + n0);
    const float* w1g  = pair ? (Wobs2 + 512 + (n0 - 512)) : (W31 + 512 + n0);

    const int lm = tid >> 2;
    const int lq = tid & 3;
    const __half* aG = &g_h [(size_t)(m0 + lm) * H1 + lq * 8];
    const __half* bG = &g_wh[(size_t)(n0 + lm) * H1 + lq * 8];

    uint32_t smem_base;
    asm("{ .reg .u64 t; cvta.to.shared.u64 t, %1; cvt.u32.u64 %0, t; }"
        : "=r"(smem_base) : "l"(smh));
    const uint32_t dOff = (uint32_t)(lm * SSTRH * 2 + lq * 16);

    // ---- per-lane ldmatrix row addresses (byte offsets within a tile) ----
    const int lr  = lane & 7;        // row within 8x8 matrix
    const int sel = lane >> 3;       // which of the 4 matrices
    // A, m-tile mt: row = wm + mt*16 + lr + (sel&1)*8, col halfs = (sel>>1)*8
    uint32_t aOffL[2];
#pragma unroll
    for (int mt = 0; mt < 2; mt++)
        aOffL[mt] = (uint32_t)(((wm + mt * 16 + lr + (sel & 1) * 8) * SSTRH
                               + (sel >> 1) * 8) * 2);
    // B, nt-pair np (covers nt=2np, 2np+1): n = wn + np*16 + lr + (sel>>1)*8,
    // col halfs = (sel&1)*8
    uint32_t bOffL[4];
#pragma unroll
    for (int np = 0; np < 4; np++)
        bOffL[np] = (uint32_t)(TILE_B + ((wn + np * 16 + lr + (sel >> 1) * 8) * SSTRH
                               + (sel & 1) * 8) * 2);

    float acc[2][8][4];
#pragma unroll
    for (int mt = 0; mt < 2; mt++)
#pragma unroll
        for (int nt = 0; nt < 8; nt++)
#pragma unroll
            for (int j = 0; j < 4; j++) acc[mt][nt][j] = 0.0f;

#pragma unroll
    for (int p = 0; p < 3; p++) {
        const uint32_t aB = smem_base + p * STAGE_B + dOff;
        const uint32_t bB = aB + (uint32_t)TILE_B;
        const int k0 = p * 32;
#pragma unroll
        for (int i = 0; i < 2; i++) {
            cpa_cg(aB + i * 64 * SSTRH * 2, aG + (size_t)i * 64 * H1 + k0);
            cpa_ca(bB + i * 64 * SSTRH * 2, bG + (size_t)i * 64 * H1 + k0);
        }
        asm volatile("cp.async.commit_group;");
    }

    for (int s = 0; s < 32; s++) {
        const int stg = s & 3;
        asm volatile("cp.async.wait_group 2;");
        __syncthreads();

        if (s + 3 < 32) {
            const int pst = (s + 3) & 3;
            const uint32_t aB = smem_base + pst * STAGE_B + dOff;
            const uint32_t bB = aB + (uint32_t)TILE_B;
            const int k0 = (s + 3) * 32;
#pragma unroll
            for (int i = 0; i < 2; i++) {
                cpa_cg(aB + i * 64 * SSTRH * 2, aG + (size_t)i * 64 * H1 + k0);
                cpa_ca(bB + i * 64 * SSTRH * 2, bG + (size_t)i * 64 * H1 + k0);
            }
        }
        asm volatile("cp.async.commit_group;");

        // ---- compute stage stg: 2 k-steps, ldmatrix fragments ----
        {
            const uint32_t tb = smem_base + stg * STAGE_B;
#pragma unroll
            for (int ks = 0; ks < 2; ks++) {
                const uint32_t kb = tb + ks * 32;   // 16 halfs = 32 bytes
                uint32_t af[2][4];
                ldmx4(af[0], kb + aOffL[0]);
                ldmx4(af[1], kb + aOffL[1]);
#pragma unroll
                for (int np = 0; np < 4; np++) {
                    uint32_t bf[4];
                    ldmx4(bf, kb + bOffL[np]);
                    mma16(acc[0][2 * np + 0], af[0], bf);
                    mma16(acc[0][2 * np + 1], af[0], bf + 2);
                    mma16(acc[1][2 * np + 0], af[1], bf);
                    mma16(acc[1][2 * np + 1], af[1], bf + 2);
                }
            }
        }
    }

    // ---- epilogue: relu + partial layer-3 dots ----
    if (tid < 128) ws[0][tid] = w0g[tid];
    else           ws[1][tid - 128] = w1g[tid - 128];
    __syncthreads();

    float u[4][2];
#pragma unroll
    for (int q = 0; q < 4; q++) { u[q][0] = 0.0f; u[q][1] = 0.0f; }

#pragma unroll
    for (int nt = 0; nt < 8; nt++) {
        const int col = wn + nt * 8 + t * 2;
        const float2 bb = *(const float2*)&bsrc[col];
        const float wa0 = ws[0][col], wa1 = ws[0][col + 1];
        const float wb0 = ws[1][col], wb1 = ws[1][col + 1];
#pragma unroll
        for (int q = 0; q < 4; q++) {
            const int mt = q >> 1, h = q & 1;
            const float v0 = fmaxf(acc[mt][nt][h * 2 + 0] + bb.x, 0.0f);
            const float v1 = fmaxf(acc[mt][nt][h * 2 + 1] + bb.y, 0.0f);
            u[q][0] = fmaf(v0, wa0, fmaf(v1, wa1, u[q][0]));
            u[q][1] = fmaf(v0, wb0, fmaf(v1, wb1, u[q][1]));
        }
    }

#pragma unroll
    for (int q = 0; q < 4; q++)
#pragma unroll
        for (int c = 0; c < 2; c++) {
            u[q][c] += __shfl_xor_sync(0xFFFFFFFFu, u[q][c], 1);
            u[q][c] += __shfl_xor_sync(0xFFFFFFFFu, u[q][c], 2);
        }

    if (t == 0) {
#pragma unroll
        for (int q = 0; q < 4; q++) {
            const int row = wm + (q >> 1) * 16 + (q & 1) * 8 + g;
            sred[half][row][0] = u[q][0];
            sred[half][row][1] = u[q][1];
        }
    }
    __syncthreads();

    {
        const int row = tid >> 1;
        const int c   = tid & 1;
        const float sum = sred[0][row][c] + sred[1][row][c];
        const int nb4 = blockIdx.x & 3;
        g_part[(size_t)(m0 + row) * 16 + pair * 8 + nb4 * 2 + c] = sum;
    }
}

// ---------------------------------------------------------------------------
// Kernel 3: per-row partial sum + sigmoid + CBF epilogue. grid 128, block 256.
// ---------------------------------------------------------------------------
__global__ __launch_bounds__(256) void k3_final(
    const float* __restrict__ x,
    const float* __restrict__ mean_, const float* __restrict__ stdv,
    const float* __restrict__ b31,   const float* __restrict__ bobs2,
    float* __restrict__ out)
{
    const int row = blockIdx.x * 256 + threadIdx.x;

    const float* pp = &g_part[(size_t)row * 16];
    float4 pa = *(const float4*)&pp[0];
    float4 pb = *(const float4*)&pp[4];
    float4 pc = *(const float4*)&pp[8];
    float4 pd = *(const float4*)&pp[12];

    const float x31_0 = pa.x + pa.z + pb.x + pb.z + b31[0];
    const float x31_1 = pa.y + pa.w + pb.y + pb.w + b31[1];
    const float t0    = pc.x + pc.z + pd.x + pd.z + bobs2[0];
    const float t1    = pc.y + pc.w + pd.y + pd.w + bobs2[1];
    const float p0 = 4.0f / (1.0f + expf(-t0));
    const float p1 = 4.0f / (1.0f + expf(-t1));

    const float* xr = x + (size_t)row * NUM_IN;
    float x0v[NUM_IN];
#pragma unroll
    for (int c = 2; c < NUM_IN; c++) x0v[c] = fmaf(xr[c], stdv[c], mean_[c]);

    const float theta = x0v[2];
    const float v     = x0v[3];
    const float st = sinf(theta), ct = cosf(theta);
    const float ox = x0v[4], oy = x0v[5], oth = x0v[6], ov = x0v[7];
    const float dx = -ox, dy = -oy;
    const float ost = sinf(oth), oct = cosf(oth);
    const float R2 = 0.45f * 0.45f;

    const float barrier = dx * dx + dy * dy - R2;
    const float bdot    = 2.0f * dx * (v * ct - ov * oct)
                        + 2.0f * dy * (v * st - ov * ost);
    const float Lf2b    = 2.0f * (v * v + ov * ov
                        - 2.0f * v * ov * cosf(theta + oth));
    const float Gu1 = -2.0f * dx * v * st + 2.0f * dy * v * ct;
    const float Gu2 =  2.0f * dx * ct + 2.0f * dy * st;

    const float psum  = p0 + p1;
    const float pprod = p0 * p1;

    float o[14];
    o[0]  = x31_0;
    o[1]  = x31_1;
    o[2]  = -Gu1;
    o[3]  = -Gu2;
    o[10] = Lf2b + psum * bdot + pprod * barrier;

    const float sLf2b = 2.0f * v * v;
#pragma unroll
    for (int j = 0; j < 3; j++) {
        const float sdx = -x0v[8 + 4 * j];
        const float sdy = -x0v[9 + 4 * j];
        const float sb    = sdx * sdx + sdy * sdy - R2;
        const float sbdot = 2.0f * sdx * v * ct + 2.0f * sdy * v * st;
        const float sGu1  = -2.0f * sdx * v * st + 2.0f * sdy * v * ct;
        const float sGu2  =  2.0f * sdx * ct + 2.0f * sdy * st;
        o[4 + 2 * j] = -sGu1;
        o[5 + 2 * j] = -sGu2;
        o[11 + j]    = sLf2b + psum * sbdot + pprod * sb;
    }

    float* op = out + (size_t)row * 14;
#pragma unroll
    for (int i = 0; i < 14; i++) op[i] = o[i];
}

// ---------------------------------------------------------------------------
// Launch
// ---------------------------------------------------------------------------
extern "C" void kernel_launch(void* const* d_in, const int* in_sizes, int n_in,
                              void* d_out, int out_size)
{
    const float* x      = (const float*)d_in[0];
    const float* mean_  = (const float*)d_in[2];
    const float* stdv   = (const float*)d_in[3];
    const float* W1     = (const float*)d_in[4];
    const float* b1     = (const float*)d_in[5];
    const float* W21    = (const float*)d_in[6];
    const float* b21    = (const float*)d_in[7];
    const float* W31    = (const float*)d_in[8];
    const float* b31    = (const float*)d_in[9];
    const float* Wobs1  = (const float*)d_in[10];
    const float* bobs1  = (const float*)d_in[11];
    const float* Wobs2  = (const float*)d_in[12];
    const float* bobs2  = (const float*)d_in[13];
    float* out = (float*)d_out;

    cudaFuncSetAttribute(k2_mma, cudaFuncAttributeMaxDynamicSharedMemorySize,
                         K2_SMEM_BYTES);

    k0_convert<<<1024, 256>>>(W21, Wobs1);
    k0b_convert<<<(B_ROWS + 1024 + 255) / 256, 256>>>(x, W1);
    k1_mma<<<dim3(8, B_ROWS / 128), 256>>>(b1);
    k2_mma<<<dim3(8, B_ROWS / 128), 256, K2_SMEM_BYTES>>>(b21, bobs1, W31, Wobs2);
    k3_final<<<B_ROWS / 256, 256>>>(x, mean_, stdv, b31, bobs2, out);
}

// round 11
// speedup vs baseline: 6.3476x; 1.0451x over previous
#include <cuda_runtime.h>
#include <cuda_fp16.h>
#include <math.h>
#include <stdint.h>

// ---------------------------------------------------------------------------
// LiveNet fused forward (sm_100 plain target; fp16 mma.sync + ldmatrix).
//   K0 : convert [W21;Wobs1] -> g_wh ; x -> g_xh (pad 20->32) ; W1 -> g_w1h
//   K1 : h = relu(x_pad @ W1p^T + b1) via mma -> g_h (fp16) [32768,1024]
//   K2 : persistent fp16 GEMM h @ g_wh^T (BK=32, 4-stage, R8 pipeline),
//        fused relu + layer-3 partial dots -> g_part
//   K3 : sum partials, sigmoid, CBF epilogue -> out [32768,14]
// ---------------------------------------------------------------------------

#define B_ROWS 32768
#define NUM_IN 20
#define H1     1024
#define KPAD   32

__device__ __half g_h  [(size_t)B_ROWS * H1];
__device__ __half g_wh [(size_t)1024 * H1];
__device__ __half g_xh [(size_t)B_ROWS * KPAD];
__device__ __half g_w1h[(size_t)1024 * KPAD];
__device__ float  g_part[(size_t)B_ROWS * 16];

// ---------------------------------------------------------------------------
// Kernel 0: all conversions. blocks 0..1023: weights; 1024..1155: x/W1 rows.
// ---------------------------------------------------------------------------
__global__ __launch_bounds__(256) void k0_convert(
    const float* __restrict__ W21, const float* __restrict__ Wobs1,
    const float* __restrict__ x,   const float* __restrict__ W1)
{
    if (blockIdx.x < 1024) {
        const size_t i4 = ((size_t)blockIdx.x * 256 + threadIdx.x) * 4;
        const size_t half_total = (size_t)512 * H1;
        const float* src = (i4 < half_total) ? (W21 + i4) : (Wobs1 + (i4 - half_total));
        float4 v = *(const float4*)src;
        __half2* dst = (__half2*)&g_wh[i4];
        dst[0] = __floats2half2_rn(v.x, v.y);
        dst[1] = __floats2half2_rn(v.z, v.w);
    } else {
        const int idx = (blockIdx.x - 1024) * 256 + threadIdx.x;
        const float* src;
        __half* dst;
        if (idx < B_ROWS) {
            src = x + (size_t)idx * NUM_IN;
            dst = &g_xh[(size_t)idx * KPAD];
        } else if (idx < B_ROWS + 1024) {
            src = W1 + (size_t)(idx - B_ROWS) * NUM_IN;
            dst = &g_w1h[(size_t)(idx - B_ROWS) * KPAD];
        } else {
            return;
        }
        __half2* d2 = (__half2*)dst;
#pragma unroll
        for (int j = 0; j < 10; j++) d2[j] = __floats2half2_rn(src[2 * j], src[2 * j + 1]);
#pragma unroll
        for (int j = 10; j < 16; j++) d2[j] = __floats2half2_rn(0.0f, 0.0f);
    }
}

// ---------------------------------------------------------------------------
// helpers
// ---------------------------------------------------------------------------
__device__ __forceinline__ void mma16(float* c, const uint32_t* a, const uint32_t* b) {
    asm volatile(
        "mma.sync.aligned.m16n8k16.row.col.f32.f16.f16.f32 "
        "{%0,%1,%2,%3}, {%4,%5,%6,%7}, {%8,%9}, {%0,%1,%2,%3};"
        : "+f"(c[0]), "+f"(c[1]), "+f"(c[2]), "+f"(c[3])
        : "r"(a[0]), "r"(a[1]), "r"(a[2]), "r"(a[3]), "r"(b[0]), "r"(b[1]));
}

__device__ __forceinline__ void ldmx4(uint32_t* r, uint32_t addr) {
    asm volatile("ldmatrix.sync.aligned.m8n8.x4.shared.b16 {%0,%1,%2,%3}, [%4];"
                 : "=r"(r[0]), "=r"(r[1]), "=r"(r[2]), "=r"(r[3]) : "r"(addr));
}

__device__ __forceinline__ void cpa_cg(uint32_t d, const __half* s) {
    asm volatile("cp.async.cg.shared.global [%0], [%1], 16;" :: "r"(d), "l"(s));
}
__device__ __forceinline__ void cpa_ca(uint32_t d, const __half* s) {
    asm volatile("cp.async.ca.shared.global [%0], [%1], 16;" :: "r"(d), "l"(s));
}

// ---------------------------------------------------------------------------
// Kernel 1: layer-1 via mma. BM=128, BN=128, K=32 (single slab).
// grid (8, 256), block 256.
// ---------------------------------------------------------------------------
#define K1_SSTR 40

__global__ __launch_bounds__(256) void k1_mma(const float* __restrict__ b1)
{
    __shared__ __half xa[128 * K1_SSTR];
    __shared__ __half wb[128 * K1_SSTR];
    __shared__ float  bs[128];

    const int tid  = threadIdx.x;
    const int wid  = tid >> 5;
    const int lane = tid & 31;
    const int g    = lane >> 2;
    const int t    = lane & 3;
    const int wm   = (wid & 3) * 32;
    const int wn   = (wid >> 2) * 64;

    const int m0 = blockIdx.y * 128;
    const int n0 = blockIdx.x * 128;

#pragma unroll
    for (int i = 0; i < 2; i++) {
        const int id  = tid + i * 256;
        const int row = id >> 2;
        const int q   = id & 3;
        *(uint4*)&xa[row * K1_SSTR + q * 8] =
            *(const uint4*)&g_xh[(size_t)(m0 + row) * KPAD + q * 8];
        *(uint4*)&wb[row * K1_SSTR + q * 8] =
            *(const uint4*)&g_w1h[(size_t)(n0 + row) * KPAD + q * 8];
    }
    if (tid < 128) bs[tid] = b1[n0 + tid];
    __syncthreads();

    float acc[2][8][4];
#pragma unroll
    for (int mt = 0; mt < 2; mt++)
#pragma unroll
        for (int nt = 0; nt < 8; nt++)
#pragma unroll
            for (int j = 0; j < 4; j++) acc[mt][nt][j] = 0.0f;

#pragma unroll
    for (int ks = 0; ks < 2; ks++) {
        const int kc = ks * 16 + 2 * t;
        uint32_t af[2][4];
#pragma unroll
        for (int mt = 0; mt < 2; mt++) {
            const __half* ap = xa + (wm + mt * 16 + g) * K1_SSTR + kc;
            af[mt][0] = *(const uint32_t*)(ap);
            af[mt][1] = *(const uint32_t*)(ap + 8 * K1_SSTR);
            af[mt][2] = *(const uint32_t*)(ap + 8);
            af[mt][3] = *(const uint32_t*)(ap + 8 * K1_SSTR + 8);
        }
#pragma unroll
        for (int nt = 0; nt < 8; nt++) {
            const __half* bp = wb + (wn + nt * 8 + g) * K1_SSTR + kc;
            uint32_t bf[2];
            bf[0] = *(const uint32_t*)(bp);
            bf[1] = *(const uint32_t*)(bp + 8);
            mma16(acc[0][nt], af[0], bf);
            mma16(acc[1][nt], af[1], bf);
        }
    }

#pragma unroll
    for (int nt = 0; nt < 8; nt++) {
        const int col = wn + nt * 8 + t * 2;
        const float b0 = bs[col], b1v = bs[col + 1];
#pragma unroll
        for (int q = 0; q < 4; q++) {
            const int mt = q >> 1, h = q & 1;
            const int row = m0 + wm + mt * 16 + h * 8 + g;
            const float v0 = fmaxf(acc[mt][nt][h * 2 + 0] + b0, 0.0f);
            const float v1 = fmaxf(acc[mt][nt][h * 2 + 1] + b1v, 0.0f);
            *(__half2*)&g_h[(size_t)row * H1 + n0 + col] = __floats2half2_rn(v0, v1);
        }
    }
}

// ---------------------------------------------------------------------------
// Kernel 2: persistent fp16 mma GEMM, R8 pipeline verbatim per tile.
// BM=128, BN=128, BK=32, 4-stage cp.async. grid 296, block 256.
// ---------------------------------------------------------------------------
#define SSTRH    40
#define TILE_H   (128 * SSTRH)
#define STAGE_H  (2 * TILE_H)
#define STAGE_B  (STAGE_H * 2)          // stage bytes (20480)
#define TILE_B   (TILE_H * 2)           // tile bytes  (10240)
#define K2_SMEM_BYTES (4 * STAGE_B)     // 81920
#define NTILES   2048
#define K2_GRID  296

__global__ __launch_bounds__(256, 2) void k2_mma(
    const float* __restrict__ b21,  const float* __restrict__ bobs1,
    const float* __restrict__ W31,  const float* __restrict__ Wobs2)
{
    extern __shared__ __half smh[];
    __shared__ float ws[2][128];
    __shared__ float sred[2][128][2];

    const int tid  = threadIdx.x;
    const int wid  = tid >> 5;
    const int lane = tid & 31;
    const int g    = lane >> 2;
    const int t    = lane & 3;
    const int wm   = (wid & 3) * 32;
    const int wn   = (wid >> 2) * 64;
    const int half = wid >> 2;

    uint32_t smem_base;
    asm("{ .reg .u64 t; cvta.to.shared.u64 t, %1; cvt.u32.u64 %0, t; }"
        : "=r"(smem_base) : "l"(smh));

    const int lm = tid >> 2;
    const int lq = tid & 3;
    const uint32_t dOff = (uint32_t)(lm * SSTRH * 2 + lq * 16);

    // ldmatrix per-lane offsets (within a stage) — tile-invariant
    const int lr  = lane & 7;
    const int sel = lane >> 3;
    uint32_t aOffL[2];
#pragma unroll
    for (int mt = 0; mt < 2; mt++)
        aOffL[mt] = (uint32_t)(((wm + mt * 16 + lr + (sel & 1) * 8) * SSTRH
                               + (sel >> 1) * 8) * 2);
    uint32_t bOffL[4];
#pragma unroll
    for (int np = 0; np < 4; np++)
        bOffL[np] = (uint32_t)(TILE_B + ((wn + np * 16 + lr + (sel >> 1) * 8) * SSTRH
                               + (sel & 1) * 8) * 2);

    for (int tile = blockIdx.x; tile < NTILES; tile += K2_GRID) {
        const int m0 = (tile >> 3) * 128;
        const int n0 = (tile & 7) * 128;
        const int pair = (n0 >= 512);

        const float* bsrc = pair ? (bobs1 + (n0 - 512)) : (b21 + n0);
        const float* w0g  = pair ? (Wobs2 + (n0 - 512)) : (W31 + n0);
        const float* w1g  = pair ? (Wobs2 + 512 + (n0 - 512)) : (W31 + 512 + n0);

        const __half* aG = &g_h [(size_t)(m0 + lm) * H1 + lq * 8];
        const __half* bG = &g_wh[(size_t)(n0 + lm) * H1 + lq * 8];

        float acc[2][8][4];
#pragma unroll
        for (int mt = 0; mt < 2; mt++)
#pragma unroll
            for (int nt = 0; nt < 8; nt++)
#pragma unroll
                for (int j = 0; j < 4; j++) acc[mt][nt][j] = 0.0f;

        // ---- prologue: stages 0..2 ----
#pragma unroll
        for (int p = 0; p < 3; p++) {
            const uint32_t aB = smem_base + p * STAGE_B + dOff;
            const uint32_t bB = aB + (uint32_t)TILE_B;
            const int k0 = p * 32;
#pragma unroll
            for (int i = 0; i < 2; i++) {
                cpa_cg(aB + i * 64 * SSTRH * 2, aG + (size_t)i * 64 * H1 + k0);
                cpa_ca(bB + i * 64 * SSTRH * 2, bG + (size_t)i * 64 * H1 + k0);
            }
            asm volatile("cp.async.commit_group;");
        }

        // ---- 32 slabs of BK=32 ----
        for (int s = 0; s < 32; s++) {
            const int stg = s & 3;
            asm volatile("cp.async.wait_group 2;");
            __syncthreads();

            if (s + 3 < 32) {
                const int pst = (s + 3) & 3;
                const uint32_t aB = smem_base + pst * STAGE_B + dOff;
                const uint32_t bB = aB + (uint32_t)TILE_B;
                const int k0 = (s + 3) * 32;
#pragma unroll
                for (int i = 0; i < 2; i++) {
                    cpa_cg(aB + i * 64 * SSTRH * 2, aG + (size_t)i * 64 * H1 + k0);
                    cpa_ca(bB + i * 64 * SSTRH * 2, bG + (size_t)i * 64 * H1 + k0);
                }
            }
            asm volatile("cp.async.commit_group;");

            // ---- compute stage stg: 2 k-steps ----
            {
                const uint32_t tb = smem_base + stg * STAGE_B;
#pragma unroll
                for (int ks = 0; ks < 2; ks++) {
                    const uint32_t kb = tb + ks * 32;
                    uint32_t af[2][4];
                    ldmx4(af[0], kb + aOffL[0]);
                    ldmx4(af[1], kb + aOffL[1]);
#pragma unroll
                    for (int np = 0; np < 4; np++) {
                        uint32_t bf[4];
                        ldmx4(bf, kb + bOffL[np]);
                        mma16(acc[0][2 * np + 0], af[0], bf);
                        mma16(acc[0][2 * np + 1], af[0], bf + 2);
                        mma16(acc[1][2 * np + 0], af[1], bf);
                        mma16(acc[1][2 * np + 1], af[1], bf + 2);
                    }
                }
            }
        }

        // ---- epilogue: relu + partial layer-3 dots ----
        if (tid < 128) ws[0][tid] = w0g[tid];
        else           ws[1][tid - 128] = w1g[tid - 128];
        __syncthreads();

        float u[4][2];
#pragma unroll
        for (int q = 0; q < 4; q++) { u[q][0] = 0.0f; u[q][1] = 0.0f; }

#pragma unroll
        for (int nt = 0; nt < 8; nt++) {
            const int col = wn + nt * 8 + t * 2;
            const float2 bb = *(const float2*)&bsrc[col];
            const float wa0 = ws[0][col], wa1 = ws[0][col + 1];
            const float wb0 = ws[1][col], wb1 = ws[1][col + 1];
#pragma unroll
            for (int q = 0; q < 4; q++) {
                const int mt = q >> 1, h = q & 1;
                const float v0 = fmaxf(acc[mt][nt][h * 2 + 0] + bb.x, 0.0f);
                const float v1 = fmaxf(acc[mt][nt][h * 2 + 1] + bb.y, 0.0f);
                u[q][0] = fmaf(v0, wa0, fmaf(v1, wa1, u[q][0]));
                u[q][1] = fmaf(v0, wb0, fmaf(v1, wb1, u[q][1]));
            }
        }

#pragma unroll
        for (int q = 0; q < 4; q++)
#pragma unroll
            for (int c = 0; c < 2; c++) {
                u[q][c] += __shfl_xor_sync(0xFFFFFFFFu, u[q][c], 1);
                u[q][c] += __shfl_xor_sync(0xFFFFFFFFu, u[q][c], 2);
            }

        if (t == 0) {
#pragma unroll
            for (int q = 0; q < 4; q++) {
                const int row = wm + (q >> 1) * 16 + (q & 1) * 8 + g;
                sred[half][row][0] = u[q][0];
                sred[half][row][1] = u[q][1];
            }
        }
        __syncthreads();

        {
            const int row = tid >> 1;
            const int c   = tid & 1;
            const float sum = sred[0][row][c] + sred[1][row][c];
            const int nb4 = tile & 3;
            g_part[(size_t)(m0 + row) * 16 + pair * 8 + nb4 * 2 + c] = sum;
        }
        __syncthreads();
    }
}

// ---------------------------------------------------------------------------
// Kernel 3: per-row partial sum + sigmoid + CBF epilogue. grid 128, block 256.
// ---------------------------------------------------------------------------
__global__ __launch_bounds__(256) void k3_final(
    const float* __restrict__ x,
    const float* __restrict__ mean_, const float* __restrict__ stdv,
    const float* __restrict__ b31,   const float* __restrict__ bobs2,
    float* __restrict__ out)
{
    const int row = blockIdx.x * 256 + threadIdx.x;

    const float* pp = &g_part[(size_t)row * 16];
    float4 pa = *(const float4*)&pp[0];
    float4 pb = *(const float4*)&pp[4];
    float4 pc = *(const float4*)&pp[8];
    float4 pd = *(const float4*)&pp[12];

    const float x31_0 = pa.x + pa.z + pb.x + pb.z + b31[0];
    const float x31_1 = pa.y + pa.w + pb.y + pb.w + b31[1];
    const float t0    = pc.x + pc.z + pd.x + pd.z + bobs2[0];
    const float t1    = pc.y + pc.w + pd.y + pd.w + bobs2[1];
    const float p0 = 4.0f / (1.0f + expf(-t0));
    const float p1 = 4.0f / (1.0f + expf(-t1));

    const float* xr = x + (size_t)row * NUM_IN;
    float x0v[NUM_IN];
#pragma unroll
    for (int c = 2; c < NUM_IN; c++) x0v[c] = fmaf(xr[c], stdv[c], mean_[c]);

    const float theta = x0v[2];
    const float v     = x0v[3];
    const float st = sinf(theta), ct = cosf(theta);
    const float ox = x0v[4], oy = x0v[5], oth = x0v[6], ov = x0v[7];
    const float dx = -ox, dy = -oy;
    const float ost = sinf(oth), oct = cosf(oth);
    const float R2 = 0.45f * 0.45f;

    const float barrier = dx * dx + dy * dy - R2;
    const float bdot    = 2.0f * dx * (v * ct - ov * oct)
                        + 2.0f * dy * (v * st - ov * ost);
    const float Lf2b    = 2.0f * (v * v + ov * ov
                        - 2.0f * v * ov * cosf(theta + oth));
    const float Gu1 = -2.0f * dx * v * st + 2.0f * dy * v * ct;
    const float Gu2 =  2.0f * dx * ct + 2.0f * dy * st;

    const float psum  = p0 + p1;
    const float pprod = p0 * p1;

    float o[14];
    o[0]  = x31_0;
    o[1]  = x31_1;
    o[2]  = -Gu1;
    o[3]  = -Gu2;
    o[10] = Lf2b + psum * bdot + pprod * barrier;

    const float sLf2b = 2.0f * v * v;
#pragma unroll
    for (int j = 0; j < 3; j++) {
        const float sdx = -x0v[8 + 4 * j];
        const float sdy = -x0v[9 + 4 * j];
        const float sb    = sdx * sdx + sdy * sdy - R2;
        const float sbdot = 2.0f * sdx * v * ct + 2.0f * sdy * v * st;
        const float sGu1  = -2.0f * sdx * v * st + 2.0f * sdy * v * ct;
        const float sGu2  =  2.0f * sdx * ct + 2.0f * sdy * st;
        o[4 + 2 * j] = -sGu1;
        o[5 + 2 * j] = -sGu2;
        o[11 + j]    = sLf2b + psum * sbdot + pprod * sb;
    }

    float* op = out + (size_t)row * 14;
#pragma unroll
    for (int i = 0; i < 14; i++) op[i] = o[i];
}

// ---------------------------------------------------------------------------
// Launch
// ---------------------------------------------------------------------------
extern "C" void kernel_launch(void* const* d_in, const int* in_sizes, int n_in,
                              void* d_out, int out_size)
{
    const float* x      = (const float*)d_in[0];
    const float* mean_  = (const float*)d_in[2];
    const float* stdv   = (const float*)d_in[3];
    const float* W1     = (const float*)d_in[4];
    const float* b1     = (const float*)d_in[5];
    const float* W21    = (const float*)d_in[6];
    const float* b21    = (const float*)d_in[7];
    const float* W31    = (const float*)d_in[8];
    const float* b31    = (const float*)d_in[9];
    const float* Wobs1  = (const float*)d_in[10];
    const float* bobs1  = (const float*)d_in[11];
    const float* Wobs2  = (const float*)d_in[12];
    const float* bobs2  = (const float*)d_in[13];
    float* out = (float*)d_out;

    cudaFuncSetAttribute(k2_mma, cudaFuncAttributeMaxDynamicSharedMemorySize,
                         K2_SMEM_BYTES);

    k0_convert<<<1024 + (B_ROWS + 1024 + 255) / 256, 256>>>(W21, Wobs1, x, W1);
    k1_mma<<<dim3(8, B_ROWS / 128), 256>>>(b1);
    k2_mma<<<K2_GRID, 256, K2_SMEM_BYTES>>>(b21, bobs1, W31, Wobs2);
    k3_final<<<B_ROWS / 256, 256>>>(x, mean_, stdv, b31, bobs2, out);
}